// round 12
// baseline (speedup 1.0000x reference)
#include <cuda_runtime.h>
#include <math.h>
#include <stdint.h>

// Problem dims
#define Bd   8
#define Nd   1000
#define NEd  4000        // N*E
#define BNT  8000        // B*N

// k_big config: 64x64 tile, 2-stage ring, split-K x4, 256 threads
#define STAGE_FLOATS 4096   // A 64x32 + B 64x32

// ---------------- device scratch ----------------
__device__ __align__(16) float g_WgHi[192 * 192];      // [cc][k], tf32 hi
__device__ __align__(16) float g_WgLo[192 * 192];      // [cc][k], tf32 lo
__device__ __align__(16) float g_Wh2[64 * 64];         // [d][c] = W_h[c][128+d], fp32
__device__ __align__(16) float g_Wo1T[96 * 64];        // [k][d] = Wo1[d][k], fp32
__device__ __align__(16) float g_SPT[16L * 64 * NEd];  // [bd][f][j], tf32-rounded
__device__ __align__(16) float g_abuf[(long)BNT * 192];// [a_in0 | a_out0 | state] (K-part 0)
__device__ __align__(16) float g_ab2[3L * BNT * 128];  // K-parts 1..3 partials
__device__ __align__(16) float g_rz[(long)BNT * 192];  // r_pre | z_pre | h_pre(partial)
__device__ __align__(16) float g_s1[(long)BNT * 64];
__device__ __align__(16) float g_s2[(long)BNT * 64];

__device__ __forceinline__ const float* sel_state(int sel, const float* prop) {
    return sel == 0 ? prop : (sel == 1 ? (const float*)g_s1 : (const float*)g_s2);
}
__device__ __forceinline__ float to_tf32(float x) {
    float r; asm("cvt.rna.tf32.f32 %0, %1;" : "=f"(r) : "f"(x)); return r;
}
__device__ __forceinline__ uint32_t smem_u32(const void* p) {
    uint32_t a;
    asm("{ .reg .u64 t; cvta.to.shared.u64 t, %1; cvt.u32.u64 %0, t; }" : "=r"(a) : "l"(p));
    return a;
}
__device__ __forceinline__ void mma16n8k8(float* c, const uint32_t* a, const uint32_t* b) {
    asm volatile(
        "mma.sync.aligned.m16n8k8.row.col.f32.tf32.tf32.f32 "
        "{%0,%1,%2,%3}, {%4,%5,%6,%7}, {%8,%9}, {%0,%1,%2,%3};"
        : "+f"(c[0]), "+f"(c[1]), "+f"(c[2]), "+f"(c[3])
        : "r"(a[0]), "r"(a[1]), "r"(a[2]), "r"(a[3]), "r"(b[0]), "r"(b[1]));
}
__device__ __forceinline__ uint32_t f2u(float x) { return __float_as_uint(x); }

// ================= k_big: tf32 mma, split-K x4, 256 threads =================
// part z sums j-chunks; z=0 -> g_abuf cols, z>=1 -> g_ab2[z-1]
// grid (16 mtiles, 16 bd, 4 kpart), 256 threads (8 warps, 4x2 of 16x32)
__global__ void __launch_bounds__(256) k_big(const float* __restrict__ Aall) {
    __shared__ float smp[2 * STAGE_FLOATS];
    uint32_t smb = smem_u32(smp);
    const int t = threadIdx.x;
    const int wid = t >> 5, lane = t & 31;
    const int bd = blockIdx.y, dir = bd & 1, b = bd >> 1;
    const int r0 = blockIdx.x * 64;
    const int z = blockIdx.z;
    const int kbase = z ? (32 + 31 * (z - 1)) : 0;   // 0,32,63,94
    const int nkt = z ? 31 : 32;
    const int rowsValid = min(64, Nd - r0);

    const int c4 = t & 7;      // float4 index along K (0..7)
    const int rr = t >> 3;     // row slot (0..31); rows rr, rr+32
    int arow[2];
    uint32_t stsA[2], stsB[2];
    const float* bSrc[2];
    const float* aBase = Aall + ((long)b * Nd + r0) * (2L * NEd) + (long)dir * NEd
                              + kbase * 32 + c4 * 4;
    const float* bBase = g_SPT + (long)bd * 64 * NEd + kbase * 32 + c4 * 4;
#pragma unroll
    for (int j = 0; j < 2; j++) {
        int row = rr + 32 * j;
        arow[j] = (row < rowsValid) ? row : (rowsValid - 1);
        stsA[j] = (uint32_t)(row * 32 + ((c4 ^ (row & 7)) * 4)) * 4u;
        stsB[j] = (uint32_t)(2048 + row * 32 + ((c4 ^ (row & 7)) * 4)) * 4u;
        bSrc[j] = bBase + (long)row * NEd;
    }

    // prologue
#pragma unroll
    for (int j = 0; j < 2; j++)
        asm volatile("cp.async.cg.shared.global [%0], [%1], 16;"
                     :: "r"(smb + stsB[j]), "l"(bSrc[j]));
    asm volatile("cp.async.commit_group;");

    float4 cA[2];
#pragma unroll
    for (int j = 0; j < 2; j++)
        cA[j] = *(const float4*)(aBase + (long)arow[j] * (2L * NEd));

    const int wm = wid & 3, wn = wid >> 2;   // warp tile: rows [wm*16,+16), cols [wn*32,+32)
    const int g = lane >> 2, tg = lane & 3;
    int offw[8];
#pragma unroll
    for (int q = 0; q < 8; q++) offw[q] = ((q ^ g) * 4) + tg;

    float acc[4][4];
#pragma unroll
    for (int nt = 0; nt < 4; nt++)
#pragma unroll
        for (int i = 0; i < 4; i++) acc[nt][i] = 0.f;

    for (int kt = 0; kt < nkt; kt++) {
        const int cur = kt & 1;
        float* As = smp + cur * STAGE_FLOATS;
        const float* Bs = As + 2048;

        // STS A (rna-converted)
#pragma unroll
        for (int j = 0; j < 2; j++) {
            float4 v = make_float4(to_tf32(cA[j].x), to_tf32(cA[j].y),
                                   to_tf32(cA[j].z), to_tf32(cA[j].w));
            *(float4*)((char*)smp + cur * (STAGE_FLOATS * 4) + stsA[j]) = v;
        }

        if (kt + 1 < nkt) {
            const uint32_t nb = smb + ((kt + 1) & 1) * (STAGE_FLOATS * 4);
#pragma unroll
            for (int j = 0; j < 2; j++)
                asm volatile("cp.async.cg.shared.global [%0], [%1], 16;"
                             :: "r"(nb + stsB[j]), "l"(bSrc[j] + (kt + 1) * 32));
            asm volatile("cp.async.commit_group;");
#pragma unroll
            for (int j = 0; j < 2; j++)
                cA[j] = *(const float4*)(aBase + (long)arow[j] * (2L * NEd) + (kt + 1) * 32);
            asm volatile("cp.async.wait_group 1;");
        } else {
            asm volatile("cp.async.wait_group 0;");
        }
        __syncthreads();

#pragma unroll
        for (int ks = 0; ks < 4; ks++) {
            uint32_t af[4];
            {
                int r = wm * 16 + g;
                af[0] = f2u(As[r * 32 + offw[2 * ks]]);
                af[1] = f2u(As[(r + 8) * 32 + offw[2 * ks]]);
                af[2] = f2u(As[r * 32 + offw[2 * ks + 1]]);
                af[3] = f2u(As[(r + 8) * 32 + offw[2 * ks + 1]]);
            }
            uint32_t bf[4][2];
#pragma unroll
            for (int nt = 0; nt < 4; nt++) {
                int c = wn * 32 + nt * 8 + g;
                bf[nt][0] = f2u(Bs[c * 32 + offw[2 * ks]]);
                bf[nt][1] = f2u(Bs[c * 32 + offw[2 * ks + 1]]);
            }
#pragma unroll
            for (int nt = 0; nt < 4; nt++)
                mma16n8k8(acc[nt], af, bf[nt]);
        }
        __syncthreads();
    }

    const long bN0 = (long)b * Nd + r0;
    float* outp = z ? (g_ab2 + (long)(z - 1) * BNT * 128 + bN0 * 128 + dir * 64)
                    : (g_abuf + bN0 * 192 + dir * 64);
    const int ldo = z ? 128 : 192;
    {
        int rl0 = wm * 16 + g;
        int rl1 = rl0 + 8;
#pragma unroll
        for (int nt = 0; nt < 4; nt++) {
            int col = wn * 32 + nt * 8 + 2 * tg;
            if (rl0 < rowsValid)
                *(float2*)(outp + (long)rl0 * ldo + col) =
                    make_float2(acc[nt][0], acc[nt][1]);
            if (rl1 < rowsValid)
                *(float2*)(outp + (long)rl1 * ldo + col) =
                    make_float2(acc[nt][2], acc[nt][3]);
        }
    }
}

// ================= k_sproj: hi/lo 3-mma (== fp32), smem-transposed tf32 epilogue =================
// SPT[bd][f][e*1000+n] = tf32( sum_d state[b][n][d] * W[e][f][d] )
// grid (16 ntiles, 64 = bd*4+e), 128 threads (2x2 warps of 32x32)
__global__ void __launch_bounds__(128) k_sproj(const float* __restrict__ prop, int sel,
                                               const float* __restrict__ W_in,
                                               const float* __restrict__ W_out) {
    __shared__ float sm[4 * 64 * 36];
    float (*Ahi)[36] = (float(*)[36])(sm);
    float (*Alo)[36] = (float(*)[36])(sm + 2304);
    float (*Bhi)[36] = (float(*)[36])(sm + 4608);
    float (*Blo)[36] = (float(*)[36])(sm + 6912);
    const float* state = sel_state(sel, prop);
    const int t = threadIdx.x;
    const int wid = t >> 5, lane = t & 31;
    const int zi = blockIdx.y;
    const int e = zi & 3, bd = zi >> 2, dir = bd & 1, b = bd >> 1;
    const int r0 = blockIdx.x * 64;
    const int rowsV = min(64, Nd - r0);
    const float* Sg = state + ((long)b * Nd + r0) * 64;
    const float* Wg = (dir ? W_out : W_in) + e * 4096;

    const int wm = wid & 1, wn = wid >> 1;
    const int g = lane >> 2, tg = lane & 3;

    float acc[2][4][4];
#pragma unroll
    for (int mt = 0; mt < 2; mt++)
#pragma unroll
        for (int nt = 0; nt < 4; nt++)
#pragma unroll
            for (int i = 0; i < 4; i++) acc[mt][nt][i] = 0.f;

#pragma unroll
    for (int kc = 0; kc < 2; kc++) {
        if (kc) __syncthreads();
#pragma unroll
        for (int i = 0; i < 4; i++) {
            int idx = t + 128 * i;
            int row = idx >> 3, cw = idx & 7;
            int k0 = kc * 32 + cw * 4;
            int rcl = (row < rowsV) ? row : (rowsV - 1);
            float4 v = *(const float4*)(Sg + (long)rcl * 64 + k0);
            float4 h = make_float4(to_tf32(v.x), to_tf32(v.y), to_tf32(v.z), to_tf32(v.w));
            float4 l = make_float4(to_tf32(v.x - h.x), to_tf32(v.y - h.y),
                                   to_tf32(v.z - h.z), to_tf32(v.w - h.w));
            *(float4*)&Ahi[row][cw * 4] = h;
            *(float4*)&Alo[row][cw * 4] = l;
            float4 w = *(const float4*)(Wg + (long)row * 64 + k0);   // row = f
            float4 wh = make_float4(to_tf32(w.x), to_tf32(w.y), to_tf32(w.z), to_tf32(w.w));
            float4 wl = make_float4(to_tf32(w.x - wh.x), to_tf32(w.y - wh.y),
                                    to_tf32(w.z - wh.z), to_tf32(w.w - wh.w));
            *(float4*)&Bhi[row][cw * 4] = wh;
            *(float4*)&Blo[row][cw * 4] = wl;
        }
        __syncthreads();

#pragma unroll
        for (int ks = 0; ks < 4; ks++) {
            int w1 = ks * 8 + tg, w2 = w1 + 4;
            uint32_t ah[2][4], al[2][4];
#pragma unroll
            for (int mt = 0; mt < 2; mt++) {
                int r = wm * 32 + mt * 16 + g;
                ah[mt][0] = f2u(Ahi[r][w1]);     ah[mt][1] = f2u(Ahi[r + 8][w1]);
                ah[mt][2] = f2u(Ahi[r][w2]);     ah[mt][3] = f2u(Ahi[r + 8][w2]);
                al[mt][0] = f2u(Alo[r][w1]);     al[mt][1] = f2u(Alo[r + 8][w1]);
                al[mt][2] = f2u(Alo[r][w2]);     al[mt][3] = f2u(Alo[r + 8][w2]);
            }
            uint32_t bh[4][2], bl[4][2];
#pragma unroll
            for (int nt = 0; nt < 4; nt++) {
                int c = wn * 32 + nt * 8 + g;
                bh[nt][0] = f2u(Bhi[c][w1]);     bh[nt][1] = f2u(Bhi[c][w2]);
                bl[nt][0] = f2u(Blo[c][w1]);     bl[nt][1] = f2u(Blo[c][w2]);
            }
#pragma unroll
            for (int mt = 0; mt < 2; mt++)
#pragma unroll
                for (int nt = 0; nt < 4; nt++) {
                    mma16n8k8(acc[mt][nt], ah[mt], bh[nt]);
                    mma16n8k8(acc[mt][nt], al[mt], bh[nt]);
                    mma16n8k8(acc[mt][nt], ah[mt], bl[nt]);
                }
        }
    }

    // transpose C[n][f] -> Tsm[f][n]
    __syncthreads();
    float (*Tsm)[65] = (float(*)[65])sm;    // 64*65 = 4160 <= 9216
#pragma unroll
    for (int mt = 0; mt < 2; mt++) {
        int rl0 = wm * 32 + mt * 16 + g, rl1 = rl0 + 8;
#pragma unroll
        for (int nt = 0; nt < 4; nt++) {
            int col = wn * 32 + nt * 8 + 2 * tg;
            Tsm[col][rl0] = acc[mt][nt][0]; Tsm[col + 1][rl0] = acc[mt][nt][1];
            Tsm[col][rl1] = acc[mt][nt][2]; Tsm[col + 1][rl1] = acc[mt][nt][3];
        }
    }
    __syncthreads();

    const int f = t >> 1, half = t & 1;
    float* dst = g_SPT + ((long)bd * 64 + f) * NEd + (long)e * Nd + r0;
#pragma unroll
    for (int j = 0; j < 8; j++) {
        int nl = half * 32 + j * 4;
        if (nl < rowsV) {
            float4 v;
            v.x = to_tf32(Tsm[f][nl + 0]);
            v.y = to_tf32(Tsm[f][nl + 1]);
            v.z = to_tf32(Tsm[f][nl + 2]);
            v.w = to_tf32(Tsm[f][nl + 3]);
            *(float4*)(dst + nl) = v;
        }
    }
}

// ================= k_gate: 3xTF32 mma, P(8000x192) = (abuf + 3 partials) @ Wg =================
// grid (125 row-tiles, 3 col-blocks), 128 threads (2x2 warps of 32x32)
__global__ void __launch_bounds__(128) k_gate() {
    __shared__ float Ahi[64][36], Alo[64][36], Bhi[64][36], Blo[64][36];
    const int t = threadIdx.x;
    const int wid = t >> 5, lane = t & 31;
    const int r0 = blockIdx.x * 64;
    const int c0 = blockIdx.y * 64;
    const int wm = wid & 1, wn = wid >> 1;
    const int g = lane >> 2, tg = lane & 3;
    const int nkc = (c0 == 128) ? 4 : 6;   // h-cols have zero Wg rows for k>=128

    float acc[2][4][4];
#pragma unroll
    for (int mt = 0; mt < 2; mt++)
#pragma unroll
        for (int nt = 0; nt < 4; nt++)
#pragma unroll
            for (int i = 0; i < 4; i++) acc[mt][nt][i] = 0.f;

    for (int kc = 0; kc < nkc; kc++) {
        if (kc) __syncthreads();
#pragma unroll
        for (int i = 0; i < 4; i++) {
            int idx = t + 128 * i;
            int row = idx >> 3, cw = idx & 7;
            int k0 = kc * 32 + cw * 4;
            float4 v = *(const float4*)(g_abuf + (long)(r0 + row) * 192 + k0);
            if (k0 < 128) {
#pragma unroll
                for (int q = 0; q < 3; q++) {
                    float4 u = *(const float4*)(g_ab2 + (long)q * BNT * 128
                                                + (long)(r0 + row) * 128 + k0);
                    v.x += u.x; v.y += u.y; v.z += u.z; v.w += u.w;
                }
            }
            float4 h = make_float4(to_tf32(v.x), to_tf32(v.y), to_tf32(v.z), to_tf32(v.w));
            float4 l = make_float4(to_tf32(v.x - h.x), to_tf32(v.y - h.y),
                                   to_tf32(v.z - h.z), to_tf32(v.w - h.w));
            *(float4*)&Ahi[row][cw * 4] = h;
            *(float4*)&Alo[row][cw * 4] = l;
            float4 wh = *(const float4*)(g_WgHi + (long)(c0 + row) * 192 + k0);
            *(float4*)&Bhi[row][cw * 4] = wh;
            float4 wl = *(const float4*)(g_WgLo + (long)(c0 + row) * 192 + k0);
            *(float4*)&Blo[row][cw * 4] = wl;
        }
        __syncthreads();

#pragma unroll
        for (int ks = 0; ks < 4; ks++) {
            int w1 = ks * 8 + tg, w2 = w1 + 4;
            uint32_t ah[2][4], al[2][4];
#pragma unroll
            for (int mt = 0; mt < 2; mt++) {
                int r = wm * 32 + mt * 16 + g;
                ah[mt][0] = f2u(Ahi[r][w1]);     ah[mt][1] = f2u(Ahi[r + 8][w1]);
                ah[mt][2] = f2u(Ahi[r][w2]);     ah[mt][3] = f2u(Ahi[r + 8][w2]);
                al[mt][0] = f2u(Alo[r][w1]);     al[mt][1] = f2u(Alo[r + 8][w1]);
                al[mt][2] = f2u(Alo[r][w2]);     al[mt][3] = f2u(Alo[r + 8][w2]);
            }
            uint32_t bh[4][2], bl[4][2];
#pragma unroll
            for (int nt = 0; nt < 4; nt++) {
                int c = wn * 32 + nt * 8 + g;
                bh[nt][0] = f2u(Bhi[c][w1]);     bh[nt][1] = f2u(Bhi[c][w2]);
                bl[nt][0] = f2u(Blo[c][w1]);     bl[nt][1] = f2u(Blo[c][w2]);
            }
#pragma unroll
            for (int mt = 0; mt < 2; mt++)
#pragma unroll
                for (int nt = 0; nt < 4; nt++) {
                    mma16n8k8(acc[mt][nt], ah[mt], bh[nt]);
                    mma16n8k8(acc[mt][nt], al[mt], bh[nt]);
                    mma16n8k8(acc[mt][nt], ah[mt], bl[nt]);
                }
        }
    }

#pragma unroll
    for (int mt = 0; mt < 2; mt++) {
        int rl0 = wm * 32 + mt * 16 + g, rl1 = rl0 + 8;
#pragma unroll
        for (int nt = 0; nt < 4; nt++) {
            int col = c0 + wn * 32 + nt * 8 + 2 * tg;
            *(float2*)(g_rz + (long)(r0 + rl0) * 192 + col) =
                make_float2(acc[mt][nt][0], acc[mt][nt][1]);
            *(float2*)(g_rz + (long)(r0 + rl1) * 192 + col) =
                make_float2(acc[mt][nt][2], acc[mt][nt][3]);
        }
    }
}

// ================= k_finish: gates + (r*s)@Wh2 + update + abuf repack, fp32 =================
__global__ void __launch_bounds__(256) k_finish(const float* __restrict__ prop, int sel_in) {
    __shared__ float Wh2s[64][65];
    __shared__ float rss[64][65];
    const float* sIn = sel_state(sel_in, prop);
    float* sOut = (sel_in == 0) ? g_s1 : g_s2;
    const int t = threadIdx.x;
    const long grow0 = (long)blockIdx.x * 64;

    for (int i = t; i < 4096; i += 256) Wh2s[i >> 6][i & 63] = g_Wh2[i];

    const int row = t >> 2, q = t & 3;
    const long gr = grow0 + row;
#pragma unroll
    for (int jj = 0; jj < 16; jj++) {
        int d = q * 16 + jj;
        float p = g_rz[gr * 192 + d];
        float r = 1.f / (1.f + expf(-p));
        rss[row][d] = r * sIn[gr * 64 + d];
    }
    __syncthreads();

    float h2[16];
#pragma unroll
    for (int j = 0; j < 16; j++) h2[j] = 0.f;
    for (int d = 0; d < 64; d++) {
        float rv = rss[row][d];
#pragma unroll
        for (int j = 0; j < 16; j++) h2[j] += rv * Wh2s[d][q * 16 + j];
    }
#pragma unroll
    for (int j = 0; j < 16; j++) {
        int c = q * 16 + j;
        float z = 1.f / (1.f + expf(-g_rz[gr * 192 + 64 + c]));
        float h = tanhf(g_rz[gr * 192 + 128 + c] + h2[j]);
        float sc = sIn[gr * 64 + c];
        float sn = (1.f - z) * sc + z * h;
        sOut[gr * 64 + c] = sn;
        g_abuf[gr * 192 + 128 + c] = sn;
    }
}

// ================= pack + misc =================
__global__ void k_pack(const float* __restrict__ W_r, const float* __restrict__ W_z,
                       const float* __restrict__ W_h, const float* __restrict__ Wo1) {
    int idx = blockIdx.x * blockDim.x + threadIdx.x;
    if (idx < 36864) {               // WgHi/Lo: [cc][k]
        int cc = idx / 192, k = idx - cc * 192;
        float v;
        if (cc < 64) v = W_r[cc * 192 + k];
        else if (cc < 128) v = W_z[(cc - 64) * 192 + k];
        else v = (k < 128) ? W_h[(cc - 128) * 192 + k] : 0.f;
        float hi = to_tf32(v);
        g_WgHi[idx] = hi;
        g_WgLo[idx] = to_tf32(v - hi);
    } else if (idx < 40960) {        // Wh2: [d][c] = W_h[c][128+d]
        int j = idx - 36864;
        int d = j >> 6, c = j & 63;
        g_Wh2[j] = W_h[c * 192 + 128 + d];
    } else if (idx < 47104) {        // Wo1T: [k][d]
        int j = idx - 40960;
        int k = j >> 6, d = j & 63;
        g_Wo1T[j] = Wo1[d * 96 + k];
    }
}

__global__ void k_pack_state(const float* __restrict__ prop) {
    int idx = blockIdx.x * blockDim.x + threadIdx.x;
    if (idx < BNT * 64) {
        int bn = idx >> 6, d = idx & 63;
        g_abuf[(long)bn * 192 + 128 + d] = prop[idx];
    }
}

__global__ void __launch_bounds__(256) k_out(const float* __restrict__ ann,
                                             const float* __restrict__ Wo2,
                                             float* __restrict__ out) {
    __shared__ float Wo1s[96 * 64];
    __shared__ float Wo2s[64];
    __shared__ float joins[32][96];
    __shared__ float part[8];

    int tid = threadIdx.x;
    for (int i = tid; i < 96 * 64; i += 256) Wo1s[i] = g_Wo1T[i];
    if (tid < 64) Wo2s[tid] = Wo2[tid];

    int base = blockIdx.x * 32;
    for (int i = tid; i < 32 * 96; i += 256) {
        int rr = i / 96;
        int k = i - rr * 96;
        int bn = base + rr;
        joins[rr][k] = (k < 64) ? g_s2[(long)bn * 64 + k] : ann[(long)bn * 32 + (k - 64)];
    }
    __syncthreads();

    int q = tid >> 6;
    int d = tid & 63;
    for (int rr = 0; rr < 32; rr += 4) {
        int r = rr + q;
        float acc = 0.f;
#pragma unroll
        for (int k = 0; k < 96; k++) acc += joins[r][k] * Wo1s[k * 64 + d];
        float v = tanhf(acc) * Wo2s[d];
#pragma unroll
        for (int off = 16; off > 0; off >>= 1)
            v += __shfl_down_sync(0xffffffffu, v, off);
        int w = tid >> 5;
        if ((tid & 31) == 0) part[w] = v;
        __syncthreads();
        if (tid < 4) out[base + rr + tid] = part[2 * tid] + part[2 * tid + 1];
        __syncthreads();
    }
}

// ---------------- launch ----------------
extern "C" void kernel_launch(void* const* d_in, const int* in_sizes, int n_in,
                              void* d_out, int out_size) {
    const float* prop  = (const float*)d_in[0];
    const float* ann   = (const float*)d_in[1];
    const float* A     = (const float*)d_in[2];
    const float* W_in  = (const float*)d_in[3];
    const float* W_out = (const float*)d_in[4];
    const float* W_r   = (const float*)d_in[5];
    const float* W_z   = (const float*)d_in[6];
    const float* W_h   = (const float*)d_in[7];
    const float* Wo1   = (const float*)d_in[8];
    const float* Wo2   = (const float*)d_in[9];
    float* out = (float*)d_out;

    k_pack<<<(47104 + 255) / 256, 256>>>(W_r, W_z, W_h, Wo1);
    k_pack_state<<<(BNT * 64 + 255) / 256, 256>>>(prop);

    // ---- step 1 (state = prop) ----
    k_sproj<<<dim3(16, 64), 128>>>(prop, 0, W_in, W_out);
    k_big<<<dim3(16, 16, 4), 256>>>(A);
    k_gate<<<dim3(125, 3), 128>>>();
    k_finish<<<125, 256>>>(prop, 0);

    // ---- step 2 (state = g_s1) ----
    k_sproj<<<dim3(16, 64), 128>>>(prop, 1, W_in, W_out);
    k_big<<<dim3(16, 16, 4), 256>>>(A);
    k_gate<<<dim3(125, 3), 128>>>();
    k_finish<<<125, 256>>>(prop, 1);

    // ---- output head ----
    k_out<<<250, 256>>>(ann, Wo2, out);
}

// round 14
// speedup vs baseline: 1.1599x; 1.1599x over previous
#include <cuda_runtime.h>
#include <math.h>
#include <stdint.h>

// Problem dims
#define Bd   8
#define Nd   1000
#define NEd  4000        // N*E
#define BNT  8000        // B*N

// k_big config: 64x64 tile, 3-stage cp.async ring (A and B), split-K x4, 128 threads
#define STAGE_FLOATS 4096   // A 64x32 + B 64x32 (16KB)

// ---------------- device scratch ----------------
__device__ __align__(16) float g_WgHi[192 * 192];      // [cc][k], tf32 hi
__device__ __align__(16) float g_WgLo[192 * 192];      // [cc][k], tf32 lo
__device__ __align__(16) float g_Wh2[64 * 64];         // [d][c] = W_h[c][128+d], fp32
__device__ __align__(16) float g_Wo1T[96 * 64];        // [k][d] = Wo1[d][k], fp32
__device__ __align__(16) float g_SPT[16L * 64 * NEd];  // [bd][f][j], tf32-rounded
__device__ __align__(16) float g_abuf[(long)BNT * 192];// [a_in0 | a_out0 | state] (K-part 0)
__device__ __align__(16) float g_ab2[3L * BNT * 128];  // K-parts 1..3 partials
__device__ __align__(16) float g_rz[(long)BNT * 192];  // r_pre | z_pre | h_pre(partial)
__device__ __align__(16) float g_s1[(long)BNT * 64];
__device__ __align__(16) float g_s2[(long)BNT * 64];

__device__ __forceinline__ const float* sel_state(int sel, const float* prop) {
    return sel == 0 ? prop : (sel == 1 ? (const float*)g_s1 : (const float*)g_s2);
}
__device__ __forceinline__ float to_tf32(float x) {
    float r; asm("cvt.rna.tf32.f32 %0, %1;" : "=f"(r) : "f"(x)); return r;
}
__device__ __forceinline__ uint32_t smem_u32(const void* p) {
    uint32_t a;
    asm("{ .reg .u64 t; cvta.to.shared.u64 t, %1; cvt.u32.u64 %0, t; }" : "=r"(a) : "l"(p));
    return a;
}
__device__ __forceinline__ void mma16n8k8(float* c, const uint32_t* a, const uint32_t* b) {
    asm volatile(
        "mma.sync.aligned.m16n8k8.row.col.f32.tf32.tf32.f32 "
        "{%0,%1,%2,%3}, {%4,%5,%6,%7}, {%8,%9}, {%0,%1,%2,%3};"
        : "+f"(c[0]), "+f"(c[1]), "+f"(c[2]), "+f"(c[3])
        : "r"(a[0]), "r"(a[1]), "r"(a[2]), "r"(a[3]), "r"(b[0]), "r"(b[1]));
}
__device__ __forceinline__ uint32_t f2u(float x) { return __float_as_uint(x); }
__device__ __forceinline__ uint32_t f2u_tf32(float x) { return __float_as_uint(to_tf32(x)); }

// ================= k_big: tf32 mma, 3-stage cp.async (A raw + cvt at fragment load) =================
// part z sums j-chunks; z=0 -> g_abuf cols, z>=1 -> g_ab2[z-1]
// grid (16 mtiles, 16 bd, 4 kpart), 128 threads (4 warps, 2x2 of 32x32)
__global__ void __launch_bounds__(128) k_big(const float* __restrict__ Aall) {
    __shared__ float smp[3 * STAGE_FLOATS];   // 48 KB
    uint32_t smb = smem_u32(smp);
    const int t = threadIdx.x;
    const int wid = t >> 5, lane = t & 31;
    const int bd = blockIdx.y, dir = bd & 1, b = bd >> 1;
    const int r0 = blockIdx.x * 64;
    const int z = blockIdx.z;
    const int kbase = z ? (32 + 31 * (z - 1)) : 0;   // 0,32,63,94
    const int nkt = z ? 31 : 32;
    const int rowsValid = min(64, Nd - r0);

    const int c4 = t & 7;      // float4 index along K (0..7)
    const int rr = t >> 3;     // row slot (0..15); rows rr+16j
    const float* aBase = Aall + ((long)b * Nd + r0) * (2L * NEd) + (long)dir * NEd
                              + kbase * 32 + c4 * 4;
    const float* bBase = g_SPT + (long)bd * 64 * NEd + kbase * 32 + c4 * 4;

    uint32_t stsA[4], stsB[4];
    const float* aSrc[4];
    const float* bSrc[4];
#pragma unroll
    for (int j = 0; j < 4; j++) {
        int row = rr + 16 * j;
        int rcl = (row < rowsValid) ? row : (rowsValid - 1);
        stsA[j] = (uint32_t)(row * 32 + ((c4 ^ (row & 7)) * 4)) * 4u;
        stsB[j] = (uint32_t)(2048 + row * 32 + ((c4 ^ (row & 7)) * 4)) * 4u;
        aSrc[j] = aBase + (long)rcl * (2L * NEd);
        bSrc[j] = bBase + (long)row * NEd;
    }

    // issue one full stage (A raw + B) into ring slot s for K-chunk kt
#define BIG_ISSUE(s_, kt_) do {                                              \
        uint32_t sb_ = smb + (uint32_t)(s_) * (STAGE_FLOATS * 4);            \
        _Pragma("unroll")                                                    \
        for (int j_ = 0; j_ < 4; j_++) {                                     \
            asm volatile("cp.async.cg.shared.global [%0], [%1], 16;"         \
                         :: "r"(sb_ + stsA[j_]), "l"(aSrc[j_] + (kt_) * 32));\
            asm volatile("cp.async.cg.shared.global [%0], [%1], 16;"         \
                         :: "r"(sb_ + stsB[j_]), "l"(bSrc[j_] + (kt_) * 32));\
        }                                                                    \
        asm volatile("cp.async.commit_group;");                              \
    } while (0)

    // prologue: stages 0,1
    BIG_ISSUE(0, 0);
    if (nkt > 1) BIG_ISSUE(1, 1);

    const int wm = wid & 1, wn = wid >> 1;
    const int g = lane >> 2, tg = lane & 3;
    int offw[8];
#pragma unroll
    for (int q = 0; q < 8; q++) offw[q] = ((q ^ g) * 4) + tg;

    float acc[2][4][4];
#pragma unroll
    for (int mt = 0; mt < 2; mt++)
#pragma unroll
        for (int nt = 0; nt < 4; nt++)
#pragma unroll
            for (int i = 0; i < 4; i++) acc[mt][nt][i] = 0.f;

    int s = 0;      // ring slot of current K-chunk
    for (int kt = 0; kt < nkt; kt++) {
        // refill slot (s+2)%3 with chunk kt+2 (safe: last computed at kt-1, bottom sync passed)
        if (kt + 2 < nkt) {
            int sn = s + 2; if (sn >= 3) sn -= 3;
            BIG_ISSUE(sn, kt + 2);
            asm volatile("cp.async.wait_group 2;");
        } else if (kt + 1 < nkt) {
            asm volatile("cp.async.wait_group 1;");
        } else {
            asm volatile("cp.async.wait_group 0;");
        }
        __syncthreads();

        const float* As = smp + s * STAGE_FLOATS;   // raw fp32 A
        const float* Bs = As + 2048;                // pre-rounded tf32 B
#pragma unroll
        for (int ks = 0; ks < 4; ks++) {
            uint32_t af[2][4];
#pragma unroll
            for (int mt = 0; mt < 2; mt++) {
                int r = wm * 32 + mt * 16 + g;
                af[mt][0] = f2u_tf32(As[r * 32 + offw[2 * ks]]);
                af[mt][1] = f2u_tf32(As[(r + 8) * 32 + offw[2 * ks]]);
                af[mt][2] = f2u_tf32(As[r * 32 + offw[2 * ks + 1]]);
                af[mt][3] = f2u_tf32(As[(r + 8) * 32 + offw[2 * ks + 1]]);
            }
            uint32_t bf[4][2];
#pragma unroll
            for (int nt = 0; nt < 4; nt++) {
                int c = wn * 32 + nt * 8 + g;
                bf[nt][0] = f2u(Bs[c * 32 + offw[2 * ks]]);
                bf[nt][1] = f2u(Bs[c * 32 + offw[2 * ks + 1]]);
            }
#pragma unroll
            for (int mt = 0; mt < 2; mt++)
#pragma unroll
                for (int nt = 0; nt < 4; nt++)
                    mma16n8k8(acc[mt][nt], af[mt], bf[nt]);
        }
        __syncthreads();
        if (++s >= 3) s -= 3;
    }
#undef BIG_ISSUE

    const long bN0 = (long)b * Nd + r0;
    float* outp = z ? (g_ab2 + (long)(z - 1) * BNT * 128 + bN0 * 128 + dir * 64)
                    : (g_abuf + bN0 * 192 + dir * 64);
    const int ldo = z ? 128 : 192;
#pragma unroll
    for (int mt = 0; mt < 2; mt++) {
        int rl0 = wm * 32 + mt * 16 + g;
        int rl1 = rl0 + 8;
#pragma unroll
        for (int nt = 0; nt < 4; nt++) {
            int col = wn * 32 + nt * 8 + 2 * tg;
            if (rl0 < rowsValid)
                *(float2*)(outp + (long)rl0 * ldo + col) =
                    make_float2(acc[mt][nt][0], acc[mt][nt][1]);
            if (rl1 < rowsValid)
                *(float2*)(outp + (long)rl1 * ldo + col) =
                    make_float2(acc[mt][nt][2], acc[mt][nt][3]);
        }
    }
}

// ================= k_sproj: hi/lo 3-mma (== fp32), smem-transposed tf32 epilogue =================
// SPT[bd][f][e*1000+n] = tf32( sum_d state[b][n][d] * W[e][f][d] )
// grid (16 ntiles, 64 = bd*4+e), 128 threads (2x2 warps of 32x32)
__global__ void __launch_bounds__(128) k_sproj(const float* __restrict__ prop, int sel,
                                               const float* __restrict__ W_in,
                                               const float* __restrict__ W_out) {
    __shared__ float sm[4 * 64 * 36];
    float (*Ahi)[36] = (float(*)[36])(sm);
    float (*Alo)[36] = (float(*)[36])(sm + 2304);
    float (*Bhi)[36] = (float(*)[36])(sm + 4608);
    float (*Blo)[36] = (float(*)[36])(sm + 6912);
    const float* state = sel_state(sel, prop);
    const int t = threadIdx.x;
    const int wid = t >> 5, lane = t & 31;
    const int zi = blockIdx.y;
    const int e = zi & 3, bd = zi >> 2, dir = bd & 1, b = bd >> 1;
    const int r0 = blockIdx.x * 64;
    const int rowsV = min(64, Nd - r0);
    const float* Sg = state + ((long)b * Nd + r0) * 64;
    const float* Wg = (dir ? W_out : W_in) + e * 4096;

    const int wm = wid & 1, wn = wid >> 1;
    const int g = lane >> 2, tg = lane & 3;

    float acc[2][4][4];
#pragma unroll
    for (int mt = 0; mt < 2; mt++)
#pragma unroll
        for (int nt = 0; nt < 4; nt++)
#pragma unroll
            for (int i = 0; i < 4; i++) acc[mt][nt][i] = 0.f;

#pragma unroll
    for (int kc = 0; kc < 2; kc++) {
        if (kc) __syncthreads();
#pragma unroll
        for (int i = 0; i < 4; i++) {
            int idx = t + 128 * i;
            int row = idx >> 3, cw = idx & 7;
            int k0 = kc * 32 + cw * 4;
            int rcl = (row < rowsV) ? row : (rowsV - 1);
            float4 v = *(const float4*)(Sg + (long)rcl * 64 + k0);
            float4 h = make_float4(to_tf32(v.x), to_tf32(v.y), to_tf32(v.z), to_tf32(v.w));
            float4 l = make_float4(to_tf32(v.x - h.x), to_tf32(v.y - h.y),
                                   to_tf32(v.z - h.z), to_tf32(v.w - h.w));
            *(float4*)&Ahi[row][cw * 4] = h;
            *(float4*)&Alo[row][cw * 4] = l;
            float4 w = *(const float4*)(Wg + (long)row * 64 + k0);   // row = f
            float4 wh = make_float4(to_tf32(w.x), to_tf32(w.y), to_tf32(w.z), to_tf32(w.w));
            float4 wl = make_float4(to_tf32(w.x - wh.x), to_tf32(w.y - wh.y),
                                    to_tf32(w.z - wh.z), to_tf32(w.w - wh.w));
            *(float4*)&Bhi[row][cw * 4] = wh;
            *(float4*)&Blo[row][cw * 4] = wl;
        }
        __syncthreads();

#pragma unroll
        for (int ks = 0; ks < 4; ks++) {
            int w1 = ks * 8 + tg, w2 = w1 + 4;
            uint32_t ah[2][4], al[2][4];
#pragma unroll
            for (int mt = 0; mt < 2; mt++) {
                int r = wm * 32 + mt * 16 + g;
                ah[mt][0] = f2u(Ahi[r][w1]);     ah[mt][1] = f2u(Ahi[r + 8][w1]);
                ah[mt][2] = f2u(Ahi[r][w2]);     ah[mt][3] = f2u(Ahi[r + 8][w2]);
                al[mt][0] = f2u(Alo[r][w1]);     al[mt][1] = f2u(Alo[r + 8][w1]);
                al[mt][2] = f2u(Alo[r][w2]);     al[mt][3] = f2u(Alo[r + 8][w2]);
            }
            uint32_t bh[4][2], bl[4][2];
#pragma unroll
            for (int nt = 0; nt < 4; nt++) {
                int c = wn * 32 + nt * 8 + g;
                bh[nt][0] = f2u(Bhi[c][w1]);     bh[nt][1] = f2u(Bhi[c][w2]);
                bl[nt][0] = f2u(Blo[c][w1]);     bl[nt][1] = f2u(Blo[c][w2]);
            }
#pragma unroll
            for (int mt = 0; mt < 2; mt++)
#pragma unroll
                for (int nt = 0; nt < 4; nt++) {
                    mma16n8k8(acc[mt][nt], ah[mt], bh[nt]);
                    mma16n8k8(acc[mt][nt], al[mt], bh[nt]);
                    mma16n8k8(acc[mt][nt], ah[mt], bl[nt]);
                }
        }
    }

    // transpose C[n][f] -> Tsm[f][n]
    __syncthreads();
    float (*Tsm)[65] = (float(*)[65])sm;    // 64*65 = 4160 <= 9216
#pragma unroll
    for (int mt = 0; mt < 2; mt++) {
        int rl0 = wm * 32 + mt * 16 + g, rl1 = rl0 + 8;
#pragma unroll
        for (int nt = 0; nt < 4; nt++) {
            int col = wn * 32 + nt * 8 + 2 * tg;
            Tsm[col][rl0] = acc[mt][nt][0]; Tsm[col + 1][rl0] = acc[mt][nt][1];
            Tsm[col][rl1] = acc[mt][nt][2]; Tsm[col + 1][rl1] = acc[mt][nt][3];
        }
    }
    __syncthreads();

    const int f = t >> 1, half = t & 1;
    float* dst = g_SPT + ((long)bd * 64 + f) * NEd + (long)e * Nd + r0;
#pragma unroll
    for (int j = 0; j < 8; j++) {
        int nl = half * 32 + j * 4;
        if (nl < rowsV) {
            float4 v;
            v.x = to_tf32(Tsm[f][nl + 0]);
            v.y = to_tf32(Tsm[f][nl + 1]);
            v.z = to_tf32(Tsm[f][nl + 2]);
            v.w = to_tf32(Tsm[f][nl + 3]);
            *(float4*)(dst + nl) = v;
        }
    }
}

// ================= k_gate: 3xTF32 mma, P(8000x192) = (abuf + 3 partials) @ Wg =================
// grid (125 row-tiles, 3 col-blocks), 128 threads (2x2 warps of 32x32)
__global__ void __launch_bounds__(128) k_gate() {
    __shared__ float Ahi[64][36], Alo[64][36], Bhi[64][36], Blo[64][36];
    const int t = threadIdx.x;
    const int wid = t >> 5, lane = t & 31;
    const int r0 = blockIdx.x * 64;
    const int c0 = blockIdx.y * 64;
    const int wm = wid & 1, wn = wid >> 1;
    const int g = lane >> 2, tg = lane & 3;
    const int nkc = (c0 == 128) ? 4 : 6;   // h-cols have zero Wg rows for k>=128

    float acc[2][4][4];
#pragma unroll
    for (int mt = 0; mt < 2; mt++)
#pragma unroll
        for (int nt = 0; nt < 4; nt++)
#pragma unroll
            for (int i = 0; i < 4; i++) acc[mt][nt][i] = 0.f;

    for (int kc = 0; kc < nkc; kc++) {
        if (kc) __syncthreads();
#pragma unroll
        for (int i = 0; i < 4; i++) {
            int idx = t + 128 * i;
            int row = idx >> 3, cw = idx & 7;
            int k0 = kc * 32 + cw * 4;
            float4 v = *(const float4*)(g_abuf + (long)(r0 + row) * 192 + k0);
            if (k0 < 128) {
#pragma unroll
                for (int q = 0; q < 3; q++) {
                    float4 u = *(const float4*)(g_ab2 + (long)q * BNT * 128
                                                + (long)(r0 + row) * 128 + k0);
                    v.x += u.x; v.y += u.y; v.z += u.z; v.w += u.w;
                }
            }
            float4 h = make_float4(to_tf32(v.x), to_tf32(v.y), to_tf32(v.z), to_tf32(v.w));
            float4 l = make_float4(to_tf32(v.x - h.x), to_tf32(v.y - h.y),
                                   to_tf32(v.z - h.z), to_tf32(v.w - h.w));
            *(float4*)&Ahi[row][cw * 4] = h;
            *(float4*)&Alo[row][cw * 4] = l;
            float4 wh = *(const float4*)(g_WgHi + (long)(c0 + row) * 192 + k0);
            *(float4*)&Bhi[row][cw * 4] = wh;
            float4 wl = *(const float4*)(g_WgLo + (long)(c0 + row) * 192 + k0);
            *(float4*)&Blo[row][cw * 4] = wl;
        }
        __syncthreads();

#pragma unroll
        for (int ks = 0; ks < 4; ks++) {
            int w1 = ks * 8 + tg, w2 = w1 + 4;
            uint32_t ah[2][4], al[2][4];
#pragma unroll
            for (int mt = 0; mt < 2; mt++) {
                int r = wm * 32 + mt * 16 + g;
                ah[mt][0] = f2u(Ahi[r][w1]);     ah[mt][1] = f2u(Ahi[r + 8][w1]);
                ah[mt][2] = f2u(Ahi[r][w2]);     ah[mt][3] = f2u(Ahi[r + 8][w2]);
                al[mt][0] = f2u(Alo[r][w1]);     al[mt][1] = f2u(Alo[r + 8][w1]);
                al[mt][2] = f2u(Alo[r][w2]);     al[mt][3] = f2u(Alo[r + 8][w2]);
            }
            uint32_t bh[4][2], bl[4][2];
#pragma unroll
            for (int nt = 0; nt < 4; nt++) {
                int c = wn * 32 + nt * 8 + g;
                bh[nt][0] = f2u(Bhi[c][w1]);     bh[nt][1] = f2u(Bhi[c][w2]);
                bl[nt][0] = f2u(Blo[c][w1]);     bl[nt][1] = f2u(Blo[c][w2]);
            }
#pragma unroll
            for (int mt = 0; mt < 2; mt++)
#pragma unroll
                for (int nt = 0; nt < 4; nt++) {
                    mma16n8k8(acc[mt][nt], ah[mt], bh[nt]);
                    mma16n8k8(acc[mt][nt], al[mt], bh[nt]);
                    mma16n8k8(acc[mt][nt], ah[mt], bl[nt]);
                }
        }
    }

#pragma unroll
    for (int mt = 0; mt < 2; mt++) {
        int rl0 = wm * 32 + mt * 16 + g, rl1 = rl0 + 8;
#pragma unroll
        for (int nt = 0; nt < 4; nt++) {
            int col = c0 + wn * 32 + nt * 8 + 2 * tg;
            *(float2*)(g_rz + (long)(r0 + rl0) * 192 + col) =
                make_float2(acc[mt][nt][0], acc[mt][nt][1]);
            *(float2*)(g_rz + (long)(r0 + rl1) * 192 + col) =
                make_float2(acc[mt][nt][2], acc[mt][nt][3]);
        }
    }
}

// ================= k_finish: gates + (r*s)@Wh2 + update + abuf repack, fp32 =================
__global__ void __launch_bounds__(256) k_finish(const float* __restrict__ prop, int sel_in) {
    __shared__ float Wh2s[64][65];
    __shared__ float rss[64][65];
    const float* sIn = sel_state(sel_in, prop);
    float* sOut = (sel_in == 0) ? g_s1 : g_s2;
    const int t = threadIdx.x;
    const long grow0 = (long)blockIdx.x * 64;

    for (int i = t; i < 4096; i += 256) Wh2s[i >> 6][i & 63] = g_Wh2[i];

    const int row = t >> 2, q = t & 3;
    const long gr = grow0 + row;
#pragma unroll
    for (int jj = 0; jj < 16; jj++) {
        int d = q * 16 + jj;
        float p = g_rz[gr * 192 + d];
        float r = 1.f / (1.f + expf(-p));
        rss[row][d] = r * sIn[gr * 64 + d];
    }
    __syncthreads();

    float h2[16];
#pragma unroll
    for (int j = 0; j < 16; j++) h2[j] = 0.f;
    for (int d = 0; d < 64; d++) {
        float rv = rss[row][d];
#pragma unroll
        for (int j = 0; j < 16; j++) h2[j] += rv * Wh2s[d][q * 16 + j];
    }
#pragma unroll
    for (int j = 0; j < 16; j++) {
        int c = q * 16 + j;
        float z = 1.f / (1.f + expf(-g_rz[gr * 192 + 64 + c]));
        float h = tanhf(g_rz[gr * 192 + 128 + c] + h2[j]);
        float sc = sIn[gr * 64 + c];
        float sn = (1.f - z) * sc + z * h;
        sOut[gr * 64 + c] = sn;
        g_abuf[gr * 192 + 128 + c] = sn;
    }
}

// ================= pack + misc =================
__global__ void k_pack(const float* __restrict__ W_r, const float* __restrict__ W_z,
                       const float* __restrict__ W_h, const float* __restrict__ Wo1) {
    int idx = blockIdx.x * blockDim.x + threadIdx.x;
    if (idx < 36864) {               // WgHi/Lo: [cc][k]
        int cc = idx / 192, k = idx - cc * 192;
        float v;
        if (cc < 64) v = W_r[cc * 192 + k];
        else if (cc < 128) v = W_z[(cc - 64) * 192 + k];
        else v = (k < 128) ? W_h[(cc - 128) * 192 + k] : 0.f;
        float hi = to_tf32(v);
        g_WgHi[idx] = hi;
        g_WgLo[idx] = to_tf32(v - hi);
    } else if (idx < 40960) {        // Wh2: [d][c] = W_h[c][128+d]
        int j = idx - 36864;
        int d = j >> 6, c = j & 63;
        g_Wh2[j] = W_h[c * 192 + 128 + d];
    } else if (idx < 47104) {        // Wo1T: [k][d]
        int j = idx - 40960;
        int k = j >> 6, d = j & 63;
        g_Wo1T[j] = Wo1[d * 96 + k];
    }
}

__global__ void k_pack_state(const float* __restrict__ prop) {
    int idx = blockIdx.x * blockDim.x + threadIdx.x;
    if (idx < BNT * 64) {
        int bn = idx >> 6, d = idx & 63;
        g_abuf[(long)bn * 192 + 128 + d] = prop[idx];
    }
}

__global__ void __launch_bounds__(256) k_out(const float* __restrict__ ann,
                                             const float* __restrict__ Wo2,
                                             float* __restrict__ out) {
    __shared__ float Wo1s[96 * 64];
    __shared__ float Wo2s[64];
    __shared__ float joins[32][96];
    __shared__ float part[8];

    int tid = threadIdx.x;
    for (int i = tid; i < 96 * 64; i += 256) Wo1s[i] = g_Wo1T[i];
    if (tid < 64) Wo2s[tid] = Wo2[tid];

    int base = blockIdx.x * 32;
    for (int i = tid; i < 32 * 96; i += 256) {
        int rr = i / 96;
        int k = i - rr * 96;
        int bn = base + rr;
        joins[rr][k] = (k < 64) ? g_s2[(long)bn * 64 + k] : ann[(long)bn * 32 + (k - 64)];
    }
    __syncthreads();

    int q = tid >> 6;
    int d = tid & 63;
    for (int rr = 0; rr < 32; rr += 4) {
        int r = rr + q;
        float acc = 0.f;
#pragma unroll
        for (int k = 0; k < 96; k++) acc += joins[r][k] * Wo1s[k * 64 + d];
        float v = tanhf(acc) * Wo2s[d];
#pragma unroll
        for (int off = 16; off > 0; off >>= 1)
            v += __shfl_down_sync(0xffffffffu, v, off);
        int w = tid >> 5;
        if ((tid & 31) == 0) part[w] = v;
        __syncthreads();
        if (tid < 4) out[base + rr + tid] = part[2 * tid] + part[2 * tid + 1];
        __syncthreads();
    }
}

// ---------------- launch ----------------
extern "C" void kernel_launch(void* const* d_in, const int* in_sizes, int n_in,
                              void* d_out, int out_size) {
    const float* prop  = (const float*)d_in[0];
    const float* ann   = (const float*)d_in[1];
    const float* A     = (const float*)d_in[2];
    const float* W_in  = (const float*)d_in[3];
    const float* W_out = (const float*)d_in[4];
    const float* W_r   = (const float*)d_in[5];
    const float* W_z   = (const float*)d_in[6];
    const float* W_h   = (const float*)d_in[7];
    const float* Wo1   = (const float*)d_in[8];
    const float* Wo2   = (const float*)d_in[9];
    float* out = (float*)d_out;

    k_pack<<<(47104 + 255) / 256, 256>>>(W_r, W_z, W_h, Wo1);
    k_pack_state<<<(BNT * 64 + 255) / 256, 256>>>(prop);

    // ---- step 1 (state = prop) ----
    k_sproj<<<dim3(16, 64), 128>>>(prop, 0, W_in, W_out);
    k_big<<<dim3(16, 16, 4), 128>>>(A);
    k_gate<<<dim3(125, 3), 128>>>();
    k_finish<<<125, 256>>>(prop, 0);

    // ---- step 2 (state = g_s1) ----
    k_sproj<<<dim3(16, 64), 128>>>(prop, 1, W_in, W_out);
    k_big<<<dim3(16, 16, 4), 128>>>(A);
    k_gate<<<dim3(125, 3), 128>>>();
    k_finish<<<125, 256>>>(prop, 1);

    // ---- output head ----
    k_out<<<250, 256>>>(ann, Wo2, out);
}

// round 15
// speedup vs baseline: 1.1773x; 1.0150x over previous
#include <cuda_runtime.h>
#include <math.h>
#include <stdint.h>

// Problem dims
#define Bd   8
#define Nd   1000
#define NEd  4000        // N*E
#define BNT  8000        // B*N

// k_big config: 64x64 tile, 4-stage cp.async ring (A and B), split-K x4, 128 threads
#define STAGE_FLOATS 4096   // A 64x32 + B 64x32 (16KB)
#define NSTG 4
#define BIG_SMEM (NSTG * STAGE_FLOATS * 4)   // 64KB dynamic

// ---------------- device scratch ----------------
__device__ __align__(16) float g_WgHi[192 * 192];      // [cc][k], tf32 hi
__device__ __align__(16) float g_WgLo[192 * 192];      // [cc][k], tf32 lo
__device__ __align__(16) float g_Wh2[64 * 64];         // [d][c] = W_h[c][128+d], fp32
__device__ __align__(16) float g_Wo1T[96 * 64];        // [k][d] = Wo1[d][k], fp32
__device__ __align__(16) float g_SPT[16L * 64 * NEd];  // [bd][f][j], tf32-rounded
__device__ __align__(16) float g_abuf[(long)BNT * 192];// [a_in0 | a_out0 | state] (K-part 0)
__device__ __align__(16) float g_ab2[3L * BNT * 128];  // K-parts 1..3 partials
__device__ __align__(16) float g_rz[(long)BNT * 192];  // r_pre | z_pre | h_pre(partial)
__device__ __align__(16) float g_s1[(long)BNT * 64];
__device__ __align__(16) float g_s2[(long)BNT * 64];

__device__ __forceinline__ const float* sel_state(int sel, const float* prop) {
    return sel == 0 ? prop : (sel == 1 ? (const float*)g_s1 : (const float*)g_s2);
}
__device__ __forceinline__ float to_tf32(float x) {
    float r; asm("cvt.rna.tf32.f32 %0, %1;" : "=f"(r) : "f"(x)); return r;
}
__device__ __forceinline__ uint32_t smem_u32(const void* p) {
    uint32_t a;
    asm("{ .reg .u64 t; cvta.to.shared.u64 t, %1; cvt.u32.u64 %0, t; }" : "=r"(a) : "l"(p));
    return a;
}
__device__ __forceinline__ void mma16n8k8(float* c, const uint32_t* a, const uint32_t* b) {
    asm volatile(
        "mma.sync.aligned.m16n8k8.row.col.f32.tf32.tf32.f32 "
        "{%0,%1,%2,%3}, {%4,%5,%6,%7}, {%8,%9}, {%0,%1,%2,%3};"
        : "+f"(c[0]), "+f"(c[1]), "+f"(c[2]), "+f"(c[3])
        : "r"(a[0]), "r"(a[1]), "r"(a[2]), "r"(a[3]), "r"(b[0]), "r"(b[1]));
}
__device__ __forceinline__ uint32_t f2u(float x) { return __float_as_uint(x); }
__device__ __forceinline__ uint32_t f2u_tf32(float x) { return __float_as_uint(to_tf32(x)); }

// ================= k_big: tf32 mma, 4-stage cp.async ring =================
// part z sums j-chunks; z=0 -> g_abuf cols, z>=1 -> g_ab2[z-1]
// grid (16 mtiles, 16 bd, 4 kpart), 128 threads (4 warps, 2x2 of 32x32)
__global__ void __launch_bounds__(128) k_big(const float* __restrict__ Aall) {
    extern __shared__ float smp[];            // NSTG * 16KB
    uint32_t smb = smem_u32(smp);
    const int t = threadIdx.x;
    const int wid = t >> 5, lane = t & 31;
    const int bd = blockIdx.y, dir = bd & 1, b = bd >> 1;
    const int r0 = blockIdx.x * 64;
    const int z = blockIdx.z;
    const int kbase = z ? (32 + 31 * (z - 1)) : 0;   // 0,32,63,94
    const int nkt = z ? 31 : 32;
    const int rowsValid = min(64, Nd - r0);

    const int c4 = t & 7;      // float4 index along K (0..7)
    const int rr = t >> 3;     // row slot (0..15); rows rr+16j
    const float* aBase = Aall + ((long)b * Nd + r0) * (2L * NEd) + (long)dir * NEd
                              + kbase * 32 + c4 * 4;
    const float* bBase = g_SPT + (long)bd * 64 * NEd + kbase * 32 + c4 * 4;

    uint32_t stsA[4], stsB[4];
    const float* aSrc[4];
    const float* bSrc[4];
#pragma unroll
    for (int j = 0; j < 4; j++) {
        int row = rr + 16 * j;
        int rcl = (row < rowsValid) ? row : (rowsValid - 1);
        stsA[j] = (uint32_t)(row * 32 + ((c4 ^ (row & 7)) * 4)) * 4u;
        stsB[j] = (uint32_t)(2048 + row * 32 + ((c4 ^ (row & 7)) * 4)) * 4u;
        aSrc[j] = aBase + (long)rcl * (2L * NEd);
        bSrc[j] = bBase + (long)row * NEd;
    }

    // issue one full stage (A raw + B) into ring slot s for K-chunk kt
#define BIG_ISSUE(s_, kt_) do {                                              \
        uint32_t sb_ = smb + (uint32_t)(s_) * (STAGE_FLOATS * 4);            \
        _Pragma("unroll")                                                    \
        for (int j_ = 0; j_ < 4; j_++) {                                     \
            asm volatile("cp.async.cg.shared.global [%0], [%1], 16;"         \
                         :: "r"(sb_ + stsA[j_]), "l"(aSrc[j_] + (kt_) * 32));\
            asm volatile("cp.async.cg.shared.global [%0], [%1], 16;"         \
                         :: "r"(sb_ + stsB[j_]), "l"(bSrc[j_] + (kt_) * 32));\
        }                                                                    \
        asm volatile("cp.async.commit_group;");                              \
    } while (0)

    // prologue: stages 0..2 (nkt >= 31 always)
    BIG_ISSUE(0, 0);
    BIG_ISSUE(1, 1);
    BIG_ISSUE(2, 2);

    const int wm = wid & 1, wn = wid >> 1;
    const int g = lane >> 2, tg = lane & 3;
    int offw[8];
#pragma unroll
    for (int q = 0; q < 8; q++) offw[q] = ((q ^ g) * 4) + tg;

    float acc[2][4][4];
#pragma unroll
    for (int mt = 0; mt < 2; mt++)
#pragma unroll
        for (int nt = 0; nt < 4; nt++)
#pragma unroll
            for (int i = 0; i < 4; i++) acc[mt][nt][i] = 0.f;

    int s = 0;      // ring slot of current K-chunk
    for (int kt = 0; kt < nkt; kt++) {
        // refill slot (s+3)&3 with chunk kt+3 (free: held chunk kt-1, bottom sync passed)
        if (kt + 3 < nkt) {
            int sn = (s + 3) & 3;
            BIG_ISSUE(sn, kt + 3);
            asm volatile("cp.async.wait_group 3;");
        } else if (kt + 2 < nkt) {
            asm volatile("cp.async.wait_group 2;");
        } else if (kt + 1 < nkt) {
            asm volatile("cp.async.wait_group 1;");
        } else {
            asm volatile("cp.async.wait_group 0;");
        }
        __syncthreads();

        const float* As = smp + s * STAGE_FLOATS;   // raw fp32 A
        const float* Bs = As + 2048;                // pre-rounded tf32 B
#pragma unroll
        for (int ks = 0; ks < 4; ks++) {
            uint32_t af[2][4];
#pragma unroll
            for (int mt = 0; mt < 2; mt++) {
                int r = wm * 32 + mt * 16 + g;
                af[mt][0] = f2u_tf32(As[r * 32 + offw[2 * ks]]);
                af[mt][1] = f2u_tf32(As[(r + 8) * 32 + offw[2 * ks]]);
                af[mt][2] = f2u_tf32(As[r * 32 + offw[2 * ks + 1]]);
                af[mt][3] = f2u_tf32(As[(r + 8) * 32 + offw[2 * ks + 1]]);
            }
            uint32_t bf[4][2];
#pragma unroll
            for (int nt = 0; nt < 4; nt++) {
                int c = wn * 32 + nt * 8 + g;
                bf[nt][0] = f2u(Bs[c * 32 + offw[2 * ks]]);
                bf[nt][1] = f2u(Bs[c * 32 + offw[2 * ks + 1]]);
            }
#pragma unroll
            for (int mt = 0; mt < 2; mt++)
#pragma unroll
                for (int nt = 0; nt < 4; nt++)
                    mma16n8k8(acc[mt][nt], af[mt], bf[nt]);
        }
        __syncthreads();
        s = (s + 1) & 3;
    }
#undef BIG_ISSUE

    const long bN0 = (long)b * Nd + r0;
    float* outp = z ? (g_ab2 + (long)(z - 1) * BNT * 128 + bN0 * 128 + dir * 64)
                    : (g_abuf + bN0 * 192 + dir * 64);
    const int ldo = z ? 128 : 192;
#pragma unroll
    for (int mt = 0; mt < 2; mt++) {
        int rl0 = wm * 32 + mt * 16 + g;
        int rl1 = rl0 + 8;
#pragma unroll
        for (int nt = 0; nt < 4; nt++) {
            int col = wn * 32 + nt * 8 + 2 * tg;
            if (rl0 < rowsValid)
                *(float2*)(outp + (long)rl0 * ldo + col) =
                    make_float2(acc[mt][nt][0], acc[mt][nt][1]);
            if (rl1 < rowsValid)
                *(float2*)(outp + (long)rl1 * ldo + col) =
                    make_float2(acc[mt][nt][2], acc[mt][nt][3]);
        }
    }
}

// ================= k_red: abuf[:, :128] += partials (fixed order, deterministic) =================
__global__ void __launch_bounds__(256) k_red() {
    long idx = (long)blockIdx.x * 256 + threadIdx.x;   // float4 index
    if (idx < (long)BNT * 32) {
        long bn = idx >> 5;
        int c4 = (int)(idx & 31);
        float4* ap = (float4*)(g_abuf + bn * 192) + c4;
        float4 v = *ap;
#pragma unroll
        for (int q = 0; q < 3; q++) {
            float4 u = *((const float4*)(g_ab2 + (long)q * BNT * 128 + bn * 128) + c4);
            v.x += u.x; v.y += u.y; v.z += u.z; v.w += u.w;
        }
        *ap = v;
    }
}

// ================= k_sproj: hi/lo 3-mma (== fp32), smem-transposed tf32 epilogue =================
// SPT[bd][f][e*1000+n] = tf32( sum_d state[b][n][d] * W[e][f][d] )
// grid (16 ntiles, 64 = bd*4+e), 128 threads (2x2 warps of 32x32)
__global__ void __launch_bounds__(128) k_sproj(const float* __restrict__ prop, int sel,
                                               const float* __restrict__ W_in,
                                               const float* __restrict__ W_out) {
    __shared__ float sm[4 * 64 * 36];
    float (*Ahi)[36] = (float(*)[36])(sm);
    float (*Alo)[36] = (float(*)[36])(sm + 2304);
    float (*Bhi)[36] = (float(*)[36])(sm + 4608);
    float (*Blo)[36] = (float(*)[36])(sm + 6912);
    const float* state = sel_state(sel, prop);
    const int t = threadIdx.x;
    const int wid = t >> 5, lane = t & 31;
    const int zi = blockIdx.y;
    const int e = zi & 3, bd = zi >> 2, dir = bd & 1, b = bd >> 1;
    const int r0 = blockIdx.x * 64;
    const int rowsV = min(64, Nd - r0);
    const float* Sg = state + ((long)b * Nd + r0) * 64;
    const float* Wg = (dir ? W_out : W_in) + e * 4096;

    const int wm = wid & 1, wn = wid >> 1;
    const int g = lane >> 2, tg = lane & 3;

    float acc[2][4][4];
#pragma unroll
    for (int mt = 0; mt < 2; mt++)
#pragma unroll
        for (int nt = 0; nt < 4; nt++)
#pragma unroll
            for (int i = 0; i < 4; i++) acc[mt][nt][i] = 0.f;

#pragma unroll
    for (int kc = 0; kc < 2; kc++) {
        if (kc) __syncthreads();
#pragma unroll
        for (int i = 0; i < 4; i++) {
            int idx = t + 128 * i;
            int row = idx >> 3, cw = idx & 7;
            int k0 = kc * 32 + cw * 4;
            int rcl = (row < rowsV) ? row : (rowsV - 1);
            float4 v = *(const float4*)(Sg + (long)rcl * 64 + k0);
            float4 h = make_float4(to_tf32(v.x), to_tf32(v.y), to_tf32(v.z), to_tf32(v.w));
            float4 l = make_float4(to_tf32(v.x - h.x), to_tf32(v.y - h.y),
                                   to_tf32(v.z - h.z), to_tf32(v.w - h.w));
            *(float4*)&Ahi[row][cw * 4] = h;
            *(float4*)&Alo[row][cw * 4] = l;
            float4 w = *(const float4*)(Wg + (long)row * 64 + k0);   // row = f
            float4 wh = make_float4(to_tf32(w.x), to_tf32(w.y), to_tf32(w.z), to_tf32(w.w));
            float4 wl = make_float4(to_tf32(w.x - wh.x), to_tf32(w.y - wh.y),
                                    to_tf32(w.z - wh.z), to_tf32(w.w - wh.w));
            *(float4*)&Bhi[row][cw * 4] = wh;
            *(float4*)&Blo[row][cw * 4] = wl;
        }
        __syncthreads();

#pragma unroll
        for (int ks = 0; ks < 4; ks++) {
            int w1 = ks * 8 + tg, w2 = w1 + 4;
            uint32_t ah[2][4], al[2][4];
#pragma unroll
            for (int mt = 0; mt < 2; mt++) {
                int r = wm * 32 + mt * 16 + g;
                ah[mt][0] = f2u(Ahi[r][w1]);     ah[mt][1] = f2u(Ahi[r + 8][w1]);
                ah[mt][2] = f2u(Ahi[r][w2]);     ah[mt][3] = f2u(Ahi[r + 8][w2]);
                al[mt][0] = f2u(Alo[r][w1]);     al[mt][1] = f2u(Alo[r + 8][w1]);
                al[mt][2] = f2u(Alo[r][w2]);     al[mt][3] = f2u(Alo[r + 8][w2]);
            }
            uint32_t bh[4][2], bl[4][2];
#pragma unroll
            for (int nt = 0; nt < 4; nt++) {
                int c = wn * 32 + nt * 8 + g;
                bh[nt][0] = f2u(Bhi[c][w1]);     bh[nt][1] = f2u(Bhi[c][w2]);
                bl[nt][0] = f2u(Blo[c][w1]);     bl[nt][1] = f2u(Blo[c][w2]);
            }
#pragma unroll
            for (int mt = 0; mt < 2; mt++)
#pragma unroll
                for (int nt = 0; nt < 4; nt++) {
                    mma16n8k8(acc[mt][nt], ah[mt], bh[nt]);
                    mma16n8k8(acc[mt][nt], al[mt], bh[nt]);
                    mma16n8k8(acc[mt][nt], ah[mt], bl[nt]);
                }
        }
    }

    // transpose C[n][f] -> Tsm[f][n]
    __syncthreads();
    float (*Tsm)[65] = (float(*)[65])sm;    // 64*65 = 4160 <= 9216
#pragma unroll
    for (int mt = 0; mt < 2; mt++) {
        int rl0 = wm * 32 + mt * 16 + g, rl1 = rl0 + 8;
#pragma unroll
        for (int nt = 0; nt < 4; nt++) {
            int col = wn * 32 + nt * 8 + 2 * tg;
            Tsm[col][rl0] = acc[mt][nt][0]; Tsm[col + 1][rl0] = acc[mt][nt][1];
            Tsm[col][rl1] = acc[mt][nt][2]; Tsm[col + 1][rl1] = acc[mt][nt][3];
        }
    }
    __syncthreads();

    const int f = t >> 1, half = t & 1;
    float* dst = g_SPT + ((long)bd * 64 + f) * NEd + (long)e * Nd + r0;
#pragma unroll
    for (int j = 0; j < 8; j++) {
        int nl = half * 32 + j * 4;
        if (nl < rowsV) {
            float4 v;
            v.x = to_tf32(Tsm[f][nl + 0]);
            v.y = to_tf32(Tsm[f][nl + 1]);
            v.z = to_tf32(Tsm[f][nl + 2]);
            v.w = to_tf32(Tsm[f][nl + 3]);
            *(float4*)(dst + nl) = v;
        }
    }
}

// ================= k_gate: 3xTF32 mma, P(8000x192) = abuf @ Wg (partials pre-reduced) =================
// grid (125 row-tiles, 3 col-blocks), 128 threads (2x2 warps of 32x32)
__global__ void __launch_bounds__(128) k_gate() {
    __shared__ float Ahi[64][36], Alo[64][36], Bhi[64][36], Blo[64][36];
    const int t = threadIdx.x;
    const int wid = t >> 5, lane = t & 31;
    const int r0 = blockIdx.x * 64;
    const int c0 = blockIdx.y * 64;
    const int wm = wid & 1, wn = wid >> 1;
    const int g = lane >> 2, tg = lane & 3;
    const int nkc = (c0 == 128) ? 4 : 6;   // h-cols have zero Wg rows for k>=128

    float acc[2][4][4];
#pragma unroll
    for (int mt = 0; mt < 2; mt++)
#pragma unroll
        for (int nt = 0; nt < 4; nt++)
#pragma unroll
            for (int i = 0; i < 4; i++) acc[mt][nt][i] = 0.f;

    for (int kc = 0; kc < nkc; kc++) {
        if (kc) __syncthreads();
#pragma unroll
        for (int i = 0; i < 4; i++) {
            int idx = t + 128 * i;
            int row = idx >> 3, cw = idx & 7;
            int k0 = kc * 32 + cw * 4;
            float4 v = *(const float4*)(g_abuf + (long)(r0 + row) * 192 + k0);
            float4 h = make_float4(to_tf32(v.x), to_tf32(v.y), to_tf32(v.z), to_tf32(v.w));
            float4 l = make_float4(to_tf32(v.x - h.x), to_tf32(v.y - h.y),
                                   to_tf32(v.z - h.z), to_tf32(v.w - h.w));
            *(float4*)&Ahi[row][cw * 4] = h;
            *(float4*)&Alo[row][cw * 4] = l;
            float4 wh = *(const float4*)(g_WgHi + (long)(c0 + row) * 192 + k0);
            *(float4*)&Bhi[row][cw * 4] = wh;
            float4 wl = *(const float4*)(g_WgLo + (long)(c0 + row) * 192 + k0);
            *(float4*)&Blo[row][cw * 4] = wl;
        }
        __syncthreads();

#pragma unroll
        for (int ks = 0; ks < 4; ks++) {
            int w1 = ks * 8 + tg, w2 = w1 + 4;
            uint32_t ah[2][4], al[2][4];
#pragma unroll
            for (int mt = 0; mt < 2; mt++) {
                int r = wm * 32 + mt * 16 + g;
                ah[mt][0] = f2u(Ahi[r][w1]);     ah[mt][1] = f2u(Ahi[r + 8][w1]);
                ah[mt][2] = f2u(Ahi[r][w2]);     ah[mt][3] = f2u(Ahi[r + 8][w2]);
                al[mt][0] = f2u(Alo[r][w1]);     al[mt][1] = f2u(Alo[r + 8][w1]);
                al[mt][2] = f2u(Alo[r][w2]);     al[mt][3] = f2u(Alo[r + 8][w2]);
            }
            uint32_t bh[4][2], bl[4][2];
#pragma unroll
            for (int nt = 0; nt < 4; nt++) {
                int c = wn * 32 + nt * 8 + g;
                bh[nt][0] = f2u(Bhi[c][w1]);     bh[nt][1] = f2u(Bhi[c][w2]);
                bl[nt][0] = f2u(Blo[c][w1]);     bl[nt][1] = f2u(Blo[c][w2]);
            }
#pragma unroll
            for (int mt = 0; mt < 2; mt++)
#pragma unroll
                for (int nt = 0; nt < 4; nt++) {
                    mma16n8k8(acc[mt][nt], ah[mt], bh[nt]);
                    mma16n8k8(acc[mt][nt], al[mt], bh[nt]);
                    mma16n8k8(acc[mt][nt], ah[mt], bl[nt]);
                }
        }
    }

#pragma unroll
    for (int mt = 0; mt < 2; mt++) {
        int rl0 = wm * 32 + mt * 16 + g, rl1 = rl0 + 8;
#pragma unroll
        for (int nt = 0; nt < 4; nt++) {
            int col = c0 + wn * 32 + nt * 8 + 2 * tg;
            *(float2*)(g_rz + (long)(r0 + rl0) * 192 + col) =
                make_float2(acc[mt][nt][0], acc[mt][nt][1]);
            *(float2*)(g_rz + (long)(r0 + rl1) * 192 + col) =
                make_float2(acc[mt][nt][2], acc[mt][nt][3]);
        }
    }
}

// ================= k_finish: gates + (r*s)@Wh2 + update + abuf repack, fp32 =================
__global__ void __launch_bounds__(256) k_finish(const float* __restrict__ prop, int sel_in) {
    __shared__ float Wh2s[64][65];
    __shared__ float rss[64][65];
    const float* sIn = sel_state(sel_in, prop);
    float* sOut = (sel_in == 0) ? g_s1 : g_s2;
    const int t = threadIdx.x;
    const long grow0 = (long)blockIdx.x * 64;

    for (int i = t; i < 4096; i += 256) Wh2s[i >> 6][i & 63] = g_Wh2[i];

    const int row = t >> 2, q = t & 3;
    const long gr = grow0 + row;
#pragma unroll
    for (int jj = 0; jj < 16; jj++) {
        int d = q * 16 + jj;
        float p = g_rz[gr * 192 + d];
        float r = 1.f / (1.f + expf(-p));
        rss[row][d] = r * sIn[gr * 64 + d];
    }
    __syncthreads();

    float h2[16];
#pragma unroll
    for (int j = 0; j < 16; j++) h2[j] = 0.f;
    for (int d = 0; d < 64; d++) {
        float rv = rss[row][d];
#pragma unroll
        for (int j = 0; j < 16; j++) h2[j] += rv * Wh2s[d][q * 16 + j];
    }
#pragma unroll
    for (int j = 0; j < 16; j++) {
        int c = q * 16 + j;
        float z = 1.f / (1.f + expf(-g_rz[gr * 192 + 64 + c]));
        float h = tanhf(g_rz[gr * 192 + 128 + c] + h2[j]);
        float sc = sIn[gr * 64 + c];
        float sn = (1.f - z) * sc + z * h;
        sOut[gr * 64 + c] = sn;
        g_abuf[gr * 192 + 128 + c] = sn;
    }
}

// ================= pack + misc =================
__global__ void k_pack(const float* __restrict__ W_r, const float* __restrict__ W_z,
                       const float* __restrict__ W_h, const float* __restrict__ Wo1) {
    int idx = blockIdx.x * blockDim.x + threadIdx.x;
    if (idx < 36864) {               // WgHi/Lo: [cc][k]
        int cc = idx / 192, k = idx - cc * 192;
        float v;
        if (cc < 64) v = W_r[cc * 192 + k];
        else if (cc < 128) v = W_z[(cc - 64) * 192 + k];
        else v = (k < 128) ? W_h[(cc - 128) * 192 + k] : 0.f;
        float hi = to_tf32(v);
        g_WgHi[idx] = hi;
        g_WgLo[idx] = to_tf32(v - hi);
    } else if (idx < 40960) {        // Wh2: [d][c] = W_h[c][128+d]
        int j = idx - 36864;
        int d = j >> 6, c = j & 63;
        g_Wh2[j] = W_h[c * 192 + 128 + d];
    } else if (idx < 47104) {        // Wo1T: [k][d]
        int j = idx - 40960;
        int k = j >> 6, d = j & 63;
        g_Wo1T[j] = Wo1[d * 96 + k];
    }
}

__global__ void k_pack_state(const float* __restrict__ prop) {
    int idx = blockIdx.x * blockDim.x + threadIdx.x;
    if (idx < BNT * 64) {
        int bn = idx >> 6, d = idx & 63;
        g_abuf[(long)bn * 192 + 128 + d] = prop[idx];
    }
}

__global__ void __launch_bounds__(256) k_out(const float* __restrict__ ann,
                                             const float* __restrict__ Wo2,
                                             float* __restrict__ out) {
    __shared__ float Wo1s[96 * 64];
    __shared__ float Wo2s[64];
    __shared__ float joins[32][96];
    __shared__ float part[8];

    int tid = threadIdx.x;
    for (int i = tid; i < 96 * 64; i += 256) Wo1s[i] = g_Wo1T[i];
    if (tid < 64) Wo2s[tid] = Wo2[tid];

    int base = blockIdx.x * 32;
    for (int i = tid; i < 32 * 96; i += 256) {
        int rr = i / 96;
        int k = i - rr * 96;
        int bn = base + rr;
        joins[rr][k] = (k < 64) ? g_s2[(long)bn * 64 + k] : ann[(long)bn * 32 + (k - 64)];
    }
    __syncthreads();

    int q = tid >> 6;
    int d = tid & 63;
    for (int rr = 0; rr < 32; rr += 4) {
        int r = rr + q;
        float acc = 0.f;
#pragma unroll
        for (int k = 0; k < 96; k++) acc += joins[r][k] * Wo1s[k * 64 + d];
        float v = tanhf(acc) * Wo2s[d];
#pragma unroll
        for (int off = 16; off > 0; off >>= 1)
            v += __shfl_down_sync(0xffffffffu, v, off);
        int w = tid >> 5;
        if ((tid & 31) == 0) part[w] = v;
        __syncthreads();
        if (tid < 4) out[base + rr + tid] = part[2 * tid] + part[2 * tid + 1];
        __syncthreads();
    }
}

// ---------------- launch ----------------
extern "C" void kernel_launch(void* const* d_in, const int* in_sizes, int n_in,
                              void* d_out, int out_size) {
    const float* prop  = (const float*)d_in[0];
    const float* ann   = (const float*)d_in[1];
    const float* A     = (const float*)d_in[2];
    const float* W_in  = (const float*)d_in[3];
    const float* W_out = (const float*)d_in[4];
    const float* W_r   = (const float*)d_in[5];
    const float* W_z   = (const float*)d_in[6];
    const float* W_h   = (const float*)d_in[7];
    const float* Wo1   = (const float*)d_in[8];
    const float* Wo2   = (const float*)d_in[9];
    float* out = (float*)d_out;

    cudaFuncSetAttribute(k_big, cudaFuncAttributeMaxDynamicSharedMemorySize, BIG_SMEM);

    k_pack<<<(47104 + 255) / 256, 256>>>(W_r, W_z, W_h, Wo1);
    k_pack_state<<<(BNT * 64 + 255) / 256, 256>>>(prop);

    // ---- step 1 (state = prop) ----
    k_sproj<<<dim3(16, 64), 128>>>(prop, 0, W_in, W_out);
    k_big<<<dim3(16, 16, 4), 128, BIG_SMEM>>>(A);
    k_red<<<1000, 256>>>();
    k_gate<<<dim3(125, 3), 128>>>();
    k_finish<<<125, 256>>>(prop, 0);

    // ---- step 2 (state = g_s1) ----
    k_sproj<<<dim3(16, 64), 128>>>(prop, 1, W_in, W_out);
    k_big<<<dim3(16, 16, 4), 128, BIG_SMEM>>>(A);
    k_red<<<1000, 256>>>();
    k_gate<<<dim3(125, 3), 128>>>();
    k_finish<<<125, 256>>>(prop, 1);

    // ---- output head ----
    k_out<<<250, 256>>>(ann, Wo2, out);
}

// round 16
// speedup vs baseline: 1.1969x; 1.0167x over previous
#include <cuda_runtime.h>
#include <math.h>
#include <stdint.h>

// Problem dims
#define Bd   8
#define Nd   1000
#define NEd  4000        // N*E
#define BNT  8000        // B*N

// k_big config: 64x64 tile, 3-stage cp.async ring (A and B), split-K x4, 128 threads
#define STAGE_FLOATS 4096   // A 64x32 + B 64x32 (16KB)

// ---------------- device scratch ----------------
__device__ __align__(16) float g_WgHi[192 * 192];      // [cc][k], tf32 hi
__device__ __align__(16) float g_WgLo[192 * 192];      // [cc][k], tf32 lo
__device__ __align__(16) float g_WHi[8 * 64 * 64];     // [dir*4+e][f][d], tf32 hi
__device__ __align__(16) float g_WLo[8 * 64 * 64];     // [dir*4+e][f][d], tf32 lo
__device__ __align__(16) float g_SH[(long)BNT * 64];   // state hi (prop, then s1)
__device__ __align__(16) float g_SL[(long)BNT * 64];   // state lo
__device__ __align__(16) float g_Wh2[64 * 64];         // [d][c] = W_h[c][128+d], fp32
__device__ __align__(16) float g_Wo1T[96 * 64];        // [k][d] = Wo1[d][k], fp32
__device__ __align__(16) float g_SPT[16L * 64 * NEd];  // [bd][f][j], tf32-rounded
__device__ __align__(16) float g_abuf[(long)BNT * 192];// [a_in0 | a_out0 | state] (K-part 0)
__device__ __align__(16) float g_ab2[3L * BNT * 128];  // K-parts 1..3 partials
__device__ __align__(16) float g_rz[(long)BNT * 192];  // r_pre | z_pre | h_pre(partial)
__device__ __align__(16) float g_s1[(long)BNT * 64];
__device__ __align__(16) float g_s2[(long)BNT * 64];

__device__ __forceinline__ const float* sel_state(int sel, const float* prop) {
    return sel == 0 ? prop : (sel == 1 ? (const float*)g_s1 : (const float*)g_s2);
}
__device__ __forceinline__ float to_tf32(float x) {
    float r; asm("cvt.rna.tf32.f32 %0, %1;" : "=f"(r) : "f"(x)); return r;
}
__device__ __forceinline__ uint32_t smem_u32(const void* p) {
    uint32_t a;
    asm("{ .reg .u64 t; cvta.to.shared.u64 t, %1; cvt.u32.u64 %0, t; }" : "=r"(a) : "l"(p));
    return a;
}
__device__ __forceinline__ void mma16n8k8(float* c, const uint32_t* a, const uint32_t* b) {
    asm volatile(
        "mma.sync.aligned.m16n8k8.row.col.f32.tf32.tf32.f32 "
        "{%0,%1,%2,%3}, {%4,%5,%6,%7}, {%8,%9}, {%0,%1,%2,%3};"
        : "+f"(c[0]), "+f"(c[1]), "+f"(c[2]), "+f"(c[3])
        : "r"(a[0]), "r"(a[1]), "r"(a[2]), "r"(a[3]), "r"(b[0]), "r"(b[1]));
}
__device__ __forceinline__ uint32_t f2u(float x) { return __float_as_uint(x); }
__device__ __forceinline__ uint32_t f2u_tf32(float x) { return __float_as_uint(to_tf32(x)); }

// ================= k_big: tf32 mma, 3-stage cp.async (A raw + cvt at fragment load) =================
// part z sums j-chunks; z=0 -> g_abuf cols, z>=1 -> g_ab2[z-1]
// grid (16 mtiles, 16 bd, 4 kpart), 128 threads (4 warps, 2x2 of 32x32)
__global__ void __launch_bounds__(128) k_big(const float* __restrict__ Aall) {
    __shared__ float smp[3 * STAGE_FLOATS];   // 48 KB
    uint32_t smb = smem_u32(smp);
    const int t = threadIdx.x;
    const int wid = t >> 5, lane = t & 31;
    const int bd = blockIdx.y, dir = bd & 1, b = bd >> 1;
    const int r0 = blockIdx.x * 64;
    const int z = blockIdx.z;
    const int kbase = z ? (32 + 31 * (z - 1)) : 0;   // 0,32,63,94
    const int nkt = z ? 31 : 32;
    const int rowsValid = min(64, Nd - r0);

    const int c4 = t & 7;      // float4 index along K (0..7)
    const int rr = t >> 3;     // row slot (0..15); rows rr+16j
    const float* aBase = Aall + ((long)b * Nd + r0) * (2L * NEd) + (long)dir * NEd
                              + kbase * 32 + c4 * 4;
    const float* bBase = g_SPT + (long)bd * 64 * NEd + kbase * 32 + c4 * 4;

    uint32_t stsA[4], stsB[4];
    const float* aSrc[4];
    const float* bSrc[4];
#pragma unroll
    for (int j = 0; j < 4; j++) {
        int row = rr + 16 * j;
        int rcl = (row < rowsValid) ? row : (rowsValid - 1);
        stsA[j] = (uint32_t)(row * 32 + ((c4 ^ (row & 7)) * 4)) * 4u;
        stsB[j] = (uint32_t)(2048 + row * 32 + ((c4 ^ (row & 7)) * 4)) * 4u;
        aSrc[j] = aBase + (long)rcl * (2L * NEd);
        bSrc[j] = bBase + (long)row * NEd;
    }

    // issue one full stage (A raw + B) into ring slot s for K-chunk kt
#define BIG_ISSUE(s_, kt_) do {                                              \
        uint32_t sb_ = smb + (uint32_t)(s_) * (STAGE_FLOATS * 4);            \
        _Pragma("unroll")                                                    \
        for (int j_ = 0; j_ < 4; j_++) {                                     \
            asm volatile("cp.async.cg.shared.global [%0], [%1], 16;"         \
                         :: "r"(sb_ + stsA[j_]), "l"(aSrc[j_] + (kt_) * 32));\
            asm volatile("cp.async.cg.shared.global [%0], [%1], 16;"         \
                         :: "r"(sb_ + stsB[j_]), "l"(bSrc[j_] + (kt_) * 32));\
        }                                                                    \
        asm volatile("cp.async.commit_group;");                              \
    } while (0)

    // prologue: stages 0,1
    BIG_ISSUE(0, 0);
    BIG_ISSUE(1, 1);

    const int wm = wid & 1, wn = wid >> 1;
    const int g = lane >> 2, tg = lane & 3;
    int offw[8];
#pragma unroll
    for (int q = 0; q < 8; q++) offw[q] = ((q ^ g) * 4) + tg;

    float acc[2][4][4];
#pragma unroll
    for (int mt = 0; mt < 2; mt++)
#pragma unroll
        for (int nt = 0; nt < 4; nt++)
#pragma unroll
            for (int i = 0; i < 4; i++) acc[mt][nt][i] = 0.f;

    int s = 0;      // ring slot of current K-chunk
    for (int kt = 0; kt < nkt; kt++) {
        if (kt + 2 < nkt) {
            int sn = s + 2; if (sn >= 3) sn -= 3;
            BIG_ISSUE(sn, kt + 2);
            asm volatile("cp.async.wait_group 2;");
        } else if (kt + 1 < nkt) {
            asm volatile("cp.async.wait_group 1;");
        } else {
            asm volatile("cp.async.wait_group 0;");
        }
        __syncthreads();

        const float* As = smp + s * STAGE_FLOATS;   // raw fp32 A
        const float* Bs = As + 2048;                // pre-rounded tf32 B
#pragma unroll
        for (int ks = 0; ks < 4; ks++) {
            uint32_t af[2][4];
#pragma unroll
            for (int mt = 0; mt < 2; mt++) {
                int r = wm * 32 + mt * 16 + g;
                af[mt][0] = f2u_tf32(As[r * 32 + offw[2 * ks]]);
                af[mt][1] = f2u_tf32(As[(r + 8) * 32 + offw[2 * ks]]);
                af[mt][2] = f2u_tf32(As[r * 32 + offw[2 * ks + 1]]);
                af[mt][3] = f2u_tf32(As[(r + 8) * 32 + offw[2 * ks + 1]]);
            }
            uint32_t bf[4][2];
#pragma unroll
            for (int nt = 0; nt < 4; nt++) {
                int c = wn * 32 + nt * 8 + g;
                bf[nt][0] = f2u(Bs[c * 32 + offw[2 * ks]]);
                bf[nt][1] = f2u(Bs[c * 32 + offw[2 * ks + 1]]);
            }
#pragma unroll
            for (int mt = 0; mt < 2; mt++)
#pragma unroll
                for (int nt = 0; nt < 4; nt++)
                    mma16n8k8(acc[mt][nt], af[mt], bf[nt]);
        }
        __syncthreads();
        if (++s >= 3) s -= 3;
    }
#undef BIG_ISSUE

    const long bN0 = (long)b * Nd + r0;
    float* outp = z ? (g_ab2 + (long)(z - 1) * BNT * 128 + bN0 * 128 + dir * 64)
                    : (g_abuf + bN0 * 192 + dir * 64);
    const int ldo = z ? 128 : 192;
#pragma unroll
    for (int mt = 0; mt < 2; mt++) {
        int rl0 = wm * 32 + mt * 16 + g;
        int rl1 = rl0 + 8;
#pragma unroll
        for (int nt = 0; nt < 4; nt++) {
            int col = wn * 32 + nt * 8 + 2 * tg;
            if (rl0 < rowsValid)
                *(float2*)(outp + (long)rl0 * ldo + col) =
                    make_float2(acc[mt][nt][0], acc[mt][nt][1]);
            if (rl1 < rowsValid)
                *(float2*)(outp + (long)rl1 * ldo + col) =
                    make_float2(acc[mt][nt][2], acc[mt][nt][3]);
        }
    }
}

// ================= k_red: abuf[:, :128] += partials (fixed order, deterministic) =================
__global__ void __launch_bounds__(256) k_red() {
    long idx = (long)blockIdx.x * 256 + threadIdx.x;   // float4 index
    if (idx < (long)BNT * 32) {
        long bn = idx >> 5;
        int c4 = (int)(idx & 31);
        float4* ap = (float4*)(g_abuf + bn * 192) + c4;
        float4 v = *ap;
#pragma unroll
        for (int q = 0; q < 3; q++) {
            float4 u = *((const float4*)(g_ab2 + (long)q * BNT * 128 + bn * 128) + c4);
            v.x += u.x; v.y += u.y; v.z += u.z; v.w += u.w;
        }
        *ap = v;
    }
}

// ================= k_sproj: hi/lo 3-mma (== fp32), pre-split operands, no load-side cvt =================
// SPT[bd][f][e*1000+n] = tf32( sum_d state[b][n][d] * W[e][f][d] )
// grid (16 ntiles, 64 = bd*4+e), 128 threads (2x2 warps of 32x32)
__global__ void __launch_bounds__(128) k_sproj(int sel) {
    __shared__ float sm[4 * 64 * 36];
    float (*Ahi)[36] = (float(*)[36])(sm);
    float (*Alo)[36] = (float(*)[36])(sm + 2304);
    float (*Bhi)[36] = (float(*)[36])(sm + 4608);
    float (*Blo)[36] = (float(*)[36])(sm + 6912);
    const int t = threadIdx.x;
    const int wid = t >> 5, lane = t & 31;
    const int zi = blockIdx.y;
    const int e = zi & 3, bd = zi >> 2, dir = bd & 1, b = bd >> 1;
    const int r0 = blockIdx.x * 64;
    const int rowsV = min(64, Nd - r0);
    const long sBase = ((long)b * Nd + r0) * 64;
    const int wOff = (dir * 4 + e) * 4096;
    (void)sel;   // g_SH/g_SL always hold the right state for this step

    const int wm = wid & 1, wn = wid >> 1;
    const int g = lane >> 2, tg = lane & 3;

    float acc[2][4][4];
#pragma unroll
    for (int mt = 0; mt < 2; mt++)
#pragma unroll
        for (int nt = 0; nt < 4; nt++)
#pragma unroll
            for (int i = 0; i < 4; i++) acc[mt][nt][i] = 0.f;

#pragma unroll
    for (int kc = 0; kc < 2; kc++) {
        if (kc) __syncthreads();
#pragma unroll
        for (int i = 0; i < 4; i++) {
            int idx = t + 128 * i;
            int row = idx >> 3, cw = idx & 7;
            int k0 = kc * 32 + cw * 4;
            int rcl = (row < rowsV) ? row : (rowsV - 1);
            *(float4*)&Ahi[row][cw * 4] = *(const float4*)(g_SH + sBase + (long)rcl * 64 + k0);
            *(float4*)&Alo[row][cw * 4] = *(const float4*)(g_SL + sBase + (long)rcl * 64 + k0);
            *(float4*)&Bhi[row][cw * 4] = *(const float4*)(g_WHi + wOff + row * 64 + k0);
            *(float4*)&Blo[row][cw * 4] = *(const float4*)(g_WLo + wOff + row * 64 + k0);
        }
        __syncthreads();

#pragma unroll
        for (int ks = 0; ks < 4; ks++) {
            int w1 = ks * 8 + tg, w2 = w1 + 4;
            uint32_t ah[2][4], al[2][4];
#pragma unroll
            for (int mt = 0; mt < 2; mt++) {
                int r = wm * 32 + mt * 16 + g;
                ah[mt][0] = f2u(Ahi[r][w1]);     ah[mt][1] = f2u(Ahi[r + 8][w1]);
                ah[mt][2] = f2u(Ahi[r][w2]);     ah[mt][3] = f2u(Ahi[r + 8][w2]);
                al[mt][0] = f2u(Alo[r][w1]);     al[mt][1] = f2u(Alo[r + 8][w1]);
                al[mt][2] = f2u(Alo[r][w2]);     al[mt][3] = f2u(Alo[r + 8][w2]);
            }
            uint32_t bh[4][2], bl[4][2];
#pragma unroll
            for (int nt = 0; nt < 4; nt++) {
                int c = wn * 32 + nt * 8 + g;
                bh[nt][0] = f2u(Bhi[c][w1]);     bh[nt][1] = f2u(Bhi[c][w2]);
                bl[nt][0] = f2u(Blo[c][w1]);     bl[nt][1] = f2u(Blo[c][w2]);
            }
#pragma unroll
            for (int mt = 0; mt < 2; mt++)
#pragma unroll
                for (int nt = 0; nt < 4; nt++) {
                    mma16n8k8(acc[mt][nt], ah[mt], bh[nt]);
                    mma16n8k8(acc[mt][nt], al[mt], bh[nt]);
                    mma16n8k8(acc[mt][nt], ah[mt], bl[nt]);
                }
        }
    }

    // transpose C[n][f] -> Tsm[f][n]
    __syncthreads();
    float (*Tsm)[65] = (float(*)[65])sm;    // 64*65 = 4160 <= 9216
#pragma unroll
    for (int mt = 0; mt < 2; mt++) {
        int rl0 = wm * 32 + mt * 16 + g, rl1 = rl0 + 8;
#pragma unroll
        for (int nt = 0; nt < 4; nt++) {
            int col = wn * 32 + nt * 8 + 2 * tg;
            Tsm[col][rl0] = acc[mt][nt][0]; Tsm[col + 1][rl0] = acc[mt][nt][1];
            Tsm[col][rl1] = acc[mt][nt][2]; Tsm[col + 1][rl1] = acc[mt][nt][3];
        }
    }
    __syncthreads();

    const int f = t >> 1, half = t & 1;
    float* dst = g_SPT + ((long)bd * 64 + f) * NEd + (long)e * Nd + r0;
#pragma unroll
    for (int j = 0; j < 8; j++) {
        int nl = half * 32 + j * 4;
        if (nl < rowsV) {
            float4 v;
            v.x = to_tf32(Tsm[f][nl + 0]);
            v.y = to_tf32(Tsm[f][nl + 1]);
            v.z = to_tf32(Tsm[f][nl + 2]);
            v.w = to_tf32(Tsm[f][nl + 3]);
            *(float4*)(dst + nl) = v;
        }
    }
}

// ================= k_gate: 3xTF32 mma, P(8000x192) = abuf @ Wg (partials pre-reduced) =================
// grid (125 row-tiles, 3 col-blocks), 128 threads (2x2 warps of 32x32)
__global__ void __launch_bounds__(128) k_gate() {
    __shared__ float Ahi[64][36], Alo[64][36], Bhi[64][36], Blo[64][36];
    const int t = threadIdx.x;
    const int wid = t >> 5, lane = t & 31;
    const int r0 = blockIdx.x * 64;
    const int c0 = blockIdx.y * 64;
    const int wm = wid & 1, wn = wid >> 1;
    const int g = lane >> 2, tg = lane & 3;
    const int nkc = (c0 == 128) ? 4 : 6;   // h-cols have zero Wg rows for k>=128

    float acc[2][4][4];
#pragma unroll
    for (int mt = 0; mt < 2; mt++)
#pragma unroll
        for (int nt = 0; nt < 4; nt++)
#pragma unroll
            for (int i = 0; i < 4; i++) acc[mt][nt][i] = 0.f;

    for (int kc = 0; kc < nkc; kc++) {
        if (kc) __syncthreads();
#pragma unroll
        for (int i = 0; i < 4; i++) {
            int idx = t + 128 * i;
            int row = idx >> 3, cw = idx & 7;
            int k0 = kc * 32 + cw * 4;
            float4 v = *(const float4*)(g_abuf + (long)(r0 + row) * 192 + k0);
            float4 h = make_float4(to_tf32(v.x), to_tf32(v.y), to_tf32(v.z), to_tf32(v.w));
            float4 l = make_float4(to_tf32(v.x - h.x), to_tf32(v.y - h.y),
                                   to_tf32(v.z - h.z), to_tf32(v.w - h.w));
            *(float4*)&Ahi[row][cw * 4] = h;
            *(float4*)&Alo[row][cw * 4] = l;
            float4 wh = *(const float4*)(g_WgHi + (long)(c0 + row) * 192 + k0);
            *(float4*)&Bhi[row][cw * 4] = wh;
            float4 wl = *(const float4*)(g_WgLo + (long)(c0 + row) * 192 + k0);
            *(float4*)&Blo[row][cw * 4] = wl;
        }
        __syncthreads();

#pragma unroll
        for (int ks = 0; ks < 4; ks++) {
            int w1 = ks * 8 + tg, w2 = w1 + 4;
            uint32_t ah[2][4], al[2][4];
#pragma unroll
            for (int mt = 0; mt < 2; mt++) {
                int r = wm * 32 + mt * 16 + g;
                ah[mt][0] = f2u(Ahi[r][w1]);     ah[mt][1] = f2u(Ahi[r + 8][w1]);
                ah[mt][2] = f2u(Ahi[r][w2]);     ah[mt][3] = f2u(Ahi[r + 8][w2]);
                al[mt][0] = f2u(Alo[r][w1]);     al[mt][1] = f2u(Alo[r + 8][w1]);
                al[mt][2] = f2u(Alo[r][w2]);     al[mt][3] = f2u(Alo[r + 8][w2]);
            }
            uint32_t bh[4][2], bl[4][2];
#pragma unroll
            for (int nt = 0; nt < 4; nt++) {
                int c = wn * 32 + nt * 8 + g;
                bh[nt][0] = f2u(Bhi[c][w1]);     bh[nt][1] = f2u(Bhi[c][w2]);
                bl[nt][0] = f2u(Blo[c][w1]);     bl[nt][1] = f2u(Blo[c][w2]);
            }
#pragma unroll
            for (int mt = 0; mt < 2; mt++)
#pragma unroll
                for (int nt = 0; nt < 4; nt++) {
                    mma16n8k8(acc[mt][nt], ah[mt], bh[nt]);
                    mma16n8k8(acc[mt][nt], al[mt], bh[nt]);
                    mma16n8k8(acc[mt][nt], ah[mt], bl[nt]);
                }
        }
    }

#pragma unroll
    for (int mt = 0; mt < 2; mt++) {
        int rl0 = wm * 32 + mt * 16 + g, rl1 = rl0 + 8;
#pragma unroll
        for (int nt = 0; nt < 4; nt++) {
            int col = c0 + wn * 32 + nt * 8 + 2 * tg;
            *(float2*)(g_rz + (long)(r0 + rl0) * 192 + col) =
                make_float2(acc[mt][nt][0], acc[mt][nt][1]);
            *(float2*)(g_rz + (long)(r0 + rl1) * 192 + col) =
                make_float2(acc[mt][nt][2], acc[mt][nt][3]);
        }
    }
}

// ================= k_finish: gates + (r*s)@Wh2 + update + abuf repack + state split, fp32 =================
__global__ void __launch_bounds__(256) k_finish(const float* __restrict__ prop, int sel_in) {
    __shared__ float Wh2s[64][65];
    __shared__ float rss[64][65];
    const float* sIn = sel_state(sel_in, prop);
    float* sOut = (sel_in == 0) ? g_s1 : g_s2;
    const int t = threadIdx.x;
    const long grow0 = (long)blockIdx.x * 64;

    for (int i = t; i < 4096; i += 256) Wh2s[i >> 6][i & 63] = g_Wh2[i];

    const int row = t >> 2, q = t & 3;
    const long gr = grow0 + row;
#pragma unroll
    for (int jj = 0; jj < 16; jj++) {
        int d = q * 16 + jj;
        float p = g_rz[gr * 192 + d];
        float r = 1.f / (1.f + expf(-p));
        rss[row][d] = r * sIn[gr * 64 + d];
    }
    __syncthreads();

    float h2[16];
#pragma unroll
    for (int j = 0; j < 16; j++) h2[j] = 0.f;
    for (int d = 0; d < 64; d++) {
        float rv = rss[row][d];
#pragma unroll
        for (int j = 0; j < 16; j++) h2[j] += rv * Wh2s[d][q * 16 + j];
    }
#pragma unroll
    for (int j = 0; j < 16; j++) {
        int c = q * 16 + j;
        float z = 1.f / (1.f + expf(-g_rz[gr * 192 + 64 + c]));
        float h = tanhf(g_rz[gr * 192 + 128 + c] + h2[j]);
        float sc = sIn[gr * 64 + c];
        float sn = (1.f - z) * sc + z * h;
        sOut[gr * 64 + c] = sn;
        g_abuf[gr * 192 + 128 + c] = sn;
        if (sel_in == 0) {          // s1 feeds step-2 sproj: store its hi/lo split
            float hi = to_tf32(sn);
            g_SH[gr * 64 + c] = hi;
            g_SL[gr * 64 + c] = to_tf32(sn - hi);
        }
    }
}

// ================= k_packall: all weight preprocessing + prop state pack/split =================
__global__ void k_packall(const float* __restrict__ prop,
                          const float* __restrict__ W_in, const float* __restrict__ W_out,
                          const float* __restrict__ W_r, const float* __restrict__ W_z,
                          const float* __restrict__ W_h, const float* __restrict__ Wo1) {
    int idx = blockIdx.x * blockDim.x + threadIdx.x;
    if (idx < 36864) {               // WgHi/Lo: [cc][k]
        int cc = idx / 192, k = idx - cc * 192;
        float v;
        if (cc < 64) v = W_r[cc * 192 + k];
        else if (cc < 128) v = W_z[(cc - 64) * 192 + k];
        else v = (k < 128) ? W_h[(cc - 128) * 192 + k] : 0.f;
        float hi = to_tf32(v);
        g_WgHi[idx] = hi;
        g_WgLo[idx] = to_tf32(v - hi);
    } else if (idx < 40960) {        // Wh2: [d][c] = W_h[c][128+d]
        int j = idx - 36864;
        int d = j >> 6, c = j & 63;
        g_Wh2[j] = W_h[c * 192 + 128 + d];
    } else if (idx < 47104) {        // Wo1T: [k][d]
        int j = idx - 40960;
        int k = j >> 6, d = j & 63;
        g_Wo1T[j] = Wo1[d * 96 + k];
    } else if (idx < 79872) {        // WHi/WLo: [dir*4+e][f][d] (same linear layout as W)
        int j = idx - 47104;
        float v = (j < 16384) ? W_in[j] : W_out[j - 16384];
        float hi = to_tf32(v);
        g_WHi[j] = hi;
        g_WLo[j] = to_tf32(v - hi);
    } else if (idx < 79872 + BNT * 64) {   // prop: abuf state slot + hi/lo split
        int j = idx - 79872;
        int bn = j >> 6, d = j & 63;
        float v = prop[j];
        g_abuf[(long)bn * 192 + 128 + d] = v;
        float hi = to_tf32(v);
        g_SH[j] = hi;
        g_SL[j] = to_tf32(v - hi);
    }
}

__global__ void __launch_bounds__(256) k_out(const float* __restrict__ ann,
                                             const float* __restrict__ Wo2,
                                             float* __restrict__ out) {
    __shared__ float Wo1s[96 * 64];
    __shared__ float Wo2s[64];
    __shared__ float joins[32][96];
    __shared__ float part[8];

    int tid = threadIdx.x;
    for (int i = tid; i < 96 * 64; i += 256) Wo1s[i] = g_Wo1T[i];
    if (tid < 64) Wo2s[tid] = Wo2[tid];

    int base = blockIdx.x * 32;
    for (int i = tid; i < 32 * 96; i += 256) {
        int rr = i / 96;
        int k = i - rr * 96;
        int bn = base + rr;
        joins[rr][k] = (k < 64) ? g_s2[(long)bn * 64 + k] : ann[(long)bn * 32 + (k - 64)];
    }
    __syncthreads();

    int q = tid >> 6;
    int d = tid & 63;
    for (int rr = 0; rr < 32; rr += 4) {
        int r = rr + q;
        float acc = 0.f;
#pragma unroll
        for (int k = 0; k < 96; k++) acc += joins[r][k] * Wo1s[k * 64 + d];
        float v = tanhf(acc) * Wo2s[d];
#pragma unroll
        for (int off = 16; off > 0; off >>= 1)
            v += __shfl_down_sync(0xffffffffu, v, off);
        int w = tid >> 5;
        if ((tid & 31) == 0) part[w] = v;
        __syncthreads();
        if (tid < 4) out[base + rr + tid] = part[2 * tid] + part[2 * tid + 1];
        __syncthreads();
    }
}

// ---------------- launch ----------------
extern "C" void kernel_launch(void* const* d_in, const int* in_sizes, int n_in,
                              void* d_out, int out_size) {
    const float* prop  = (const float*)d_in[0];
    const float* ann   = (const float*)d_in[1];
    const float* A     = (const float*)d_in[2];
    const float* W_in  = (const float*)d_in[3];
    const float* W_out = (const float*)d_in[4];
    const float* W_r   = (const float*)d_in[5];
    const float* W_z   = (const float*)d_in[6];
    const float* W_h   = (const float*)d_in[7];
    const float* Wo1   = (const float*)d_in[8];
    const float* Wo2   = (const float*)d_in[9];
    float* out = (float*)d_out;

    const int PACK_TOTAL = 79872 + BNT * 64;
    k_packall<<<(PACK_TOTAL + 255) / 256, 256>>>(prop, W_in, W_out, W_r, W_z, W_h, Wo1);

    // ---- step 1 (state = prop) ----
    k_sproj<<<dim3(16, 64), 128>>>(0);
    k_big<<<dim3(16, 16, 4), 128>>>(A);
    k_red<<<1000, 256>>>();
    k_gate<<<dim3(125, 3), 128>>>();
    k_finish<<<125, 256>>>(prop, 0);

    // ---- step 2 (state = g_s1) ----
    k_sproj<<<dim3(16, 64), 128>>>(1);
    k_big<<<dim3(16, 16, 4), 128>>>(A);
    k_red<<<1000, 256>>>();
    k_gate<<<dim3(125, 3), 128>>>();
    k_finish<<<125, 256>>>(prop, 1);

    // ---- output head ----
    k_out<<<250, 256>>>(ann, Wo2, out);
}